// round 1
// baseline (speedup 1.0000x reference)
#include <cuda_runtime.h>

// ---------------------------------------------------------------------------
// Shapes (fixed by the problem):
//   B=2048, IN_DIM=1024, HID=512, FEAT=256, OUT=2
// Pipeline:
//   K1: H_z = relu(x_z @ W_feat + b_feat)           [2048,512]  z in {0,1}
//   K2: F_z = H_z @ W_br_z + b_br_z                 [2048,256]
//   K3: U_o[b,j] = sum_i F0[b,i] * W_out[j*512 + i*2 + o]   (bilinear trick)
//   K4: out[b,o] = b_out[o] + sum_j F1[b,j] * U_o[b,j]
// ---------------------------------------------------------------------------

#define BATCH   2048
#define IN_DIM  1024
#define HID     512
#define FEAT    256

#define BM 128
#define BN 128
#define BK 16
#define TM 8
#define TN 8
// 256 threads per CTA: 16x16 grid of threads, each owns an 8x8 micro-tile.

// Scratch (no cudaMalloc allowed): H (2x 2048x512), F (2x 2048x256), U (2x 2048x256)
__device__ __align__(16) float g_H[2 * BATCH * HID];
__device__ __align__(16) float g_F[2 * BATCH * FEAT];
__device__ __align__(16) float g_U[2 * BATCH * FEAT];

// Generic tiled SGEMM: C = op(A @ B + bias), with B addressed as
//   B[k][n] = Bbase[k*sK + n*sN]
// so the same kernel handles row-major weights (sK=N, sN=1) and the strided
// W_out view for the bilinear trick (sK=2, sN=512).
// blockIdx.z selects between two independent problem instances (shared shape).
template <bool RELU, bool HAS_BIAS>
__global__ void __launch_bounds__(256)
sgemm_kernel(const float* __restrict__ A0, const float* __restrict__ A1,
             const float* __restrict__ B0, const float* __restrict__ B1,
             const float* __restrict__ bias0, const float* __restrict__ bias1,
             float* __restrict__ C0, float* __restrict__ C1,
             int M, int N, int K, int sK, int sN)
{
    const float* A    = blockIdx.z ? A1 : A0;
    const float* Bm   = blockIdx.z ? B1 : B0;
    const float* bias = blockIdx.z ? bias1 : bias0;
    float*       C    = blockIdx.z ? C1 : C0;

    __shared__ float As[BK][BM + 4];   // stored transposed: As[k][m]
    __shared__ float Bs[BK][BN + 4];

    const int tid      = threadIdx.x;
    const int rowBlock = blockIdx.y * BM;
    const int colBlock = blockIdx.x * BN;

    // A-load mapping: float4 per thread, 2 passes cover 128 rows x 16 cols
    const int aRow  = tid >> 2;          // 0..63
    const int aCol4 = (tid & 3) << 2;    // 0,4,8,12
    // B-load mapping: scalar, n contiguous across threads (coalesced if sN==1)
    const int bn  = tid & (BN - 1);      // 0..127
    const int bk0 = tid >> 7;            // 0..1

    const int rbase = (tid >> 4) * TM;   // 0..120
    const int cbase = (tid & 15) * TN;   // 0..120

    float acc[TM][TN];
    #pragma unroll
    for (int i = 0; i < TM; i++)
        #pragma unroll
        for (int j = 0; j < TN; j++)
            acc[i][j] = 0.0f;

    for (int kt = 0; kt < K; kt += BK) {
        // ---- load A tile (transposed into smem) ----
        #pragma unroll
        for (int r = 0; r < 2; r++) {
            int m = aRow + r * 64;
            float4 v = *reinterpret_cast<const float4*>(
                &A[(size_t)(rowBlock + m) * K + kt + aCol4]);
            As[aCol4 + 0][m] = v.x;
            As[aCol4 + 1][m] = v.y;
            As[aCol4 + 2][m] = v.z;
            As[aCol4 + 3][m] = v.w;
        }
        // ---- load B tile ----
        #pragma unroll
        for (int p = 0; p < 8; p++) {
            int k = bk0 + p * 2;
            Bs[k][bn] = Bm[(size_t)(kt + k) * sK + (size_t)(colBlock + bn) * sN];
        }
        __syncthreads();

        // ---- compute ----
        #pragma unroll
        for (int k = 0; k < BK; k++) {
            float ra[TM], rb[TN];
            #pragma unroll
            for (int i = 0; i < TM; i++) ra[i] = As[k][rbase + i];
            #pragma unroll
            for (int j = 0; j < TN; j++) rb[j] = Bs[k][cbase + j];
            #pragma unroll
            for (int i = 0; i < TM; i++)
                #pragma unroll
                for (int j = 0; j < TN; j++)
                    acc[i][j] = fmaf(ra[i], rb[j], acc[i][j]);
        }
        __syncthreads();
    }

    // ---- epilogue ----
    #pragma unroll
    for (int i = 0; i < TM; i++) {
        const size_t row = (size_t)(rowBlock + rbase + i);
        #pragma unroll
        for (int j = 0; j < TN; j++) {
            int col = colBlock + cbase + j;
            float v = acc[i][j];
            if (HAS_BIAS) v += bias[col];
            if (RELU)     v = fmaxf(v, 0.0f);
            C[row * N + col] = v;
        }
    }
}

// K4: one warp per batch row; both outputs at once.
__global__ void __launch_bounds__(256)
reduce_out_kernel(const float* __restrict__ F1,
                  const float* __restrict__ U0,
                  const float* __restrict__ U1,
                  const float* __restrict__ b_out,
                  float* __restrict__ out)
{
    int warp = (blockIdx.x * blockDim.x + threadIdx.x) >> 5;
    int lane = threadIdx.x & 31;
    if (warp >= BATCH) return;

    const float* f  = F1 + (size_t)warp * FEAT;
    const float* u0 = U0 + (size_t)warp * FEAT;
    const float* u1 = U1 + (size_t)warp * FEAT;

    float s0 = 0.0f, s1 = 0.0f;
    #pragma unroll
    for (int j = lane; j < FEAT; j += 32) {
        float fv = f[j];
        s0 = fmaf(fv, u0[j], s0);
        s1 = fmaf(fv, u1[j], s1);
    }
    #pragma unroll
    for (int off = 16; off; off >>= 1) {
        s0 += __shfl_down_sync(0xFFFFFFFFu, s0, off);
        s1 += __shfl_down_sync(0xFFFFFFFFu, s1, off);
    }
    if (lane == 0) {
        out[warp * 2 + 0] = s0 + b_out[0];
        out[warp * 2 + 1] = s1 + b_out[1];
    }
}

extern "C" void kernel_launch(void* const* d_in, const int* in_sizes, int n_in,
                              void* d_out, int out_size)
{
    const float* x0     = (const float*)d_in[0];
    const float* x1     = (const float*)d_in[1];
    const float* W_feat = (const float*)d_in[2];
    const float* b_feat = (const float*)d_in[3];
    const float* W_br0  = (const float*)d_in[4];
    const float* b_br0  = (const float*)d_in[5];
    const float* W_br1  = (const float*)d_in[6];
    const float* b_br1  = (const float*)d_in[7];
    const float* W_out  = (const float*)d_in[8];
    const float* b_out  = (const float*)d_in[9];
    float*       out    = (float*)d_out;

    float *H, *F, *U;
    cudaGetSymbolAddress((void**)&H, g_H);
    cudaGetSymbolAddress((void**)&F, g_F);
    cudaGetSymbolAddress((void**)&U, g_U);
    float* H0 = H;  float* H1 = H + (size_t)BATCH * HID;
    float* F0 = F;  float* F1 = F + (size_t)BATCH * FEAT;
    float* U0 = U;  float* U1 = U + (size_t)BATCH * FEAT;

    // K1: H_z = relu(x_z @ W_feat + b_feat)   M=2048 N=512 K=1024
    sgemm_kernel<true, true><<<dim3(HID / BN, BATCH / BM, 2), 256>>>(
        x0, x1, W_feat, W_feat, b_feat, b_feat, H0, H1,
        BATCH, HID, IN_DIM, HID, 1);

    // K2: F_z = H_z @ W_br_z + b_br_z         M=2048 N=256 K=512
    sgemm_kernel<false, true><<<dim3(FEAT / BN, BATCH / BM, 2), 256>>>(
        H0, H1, W_br0, W_br1, b_br0, b_br1, F0, F1,
        BATCH, FEAT, HID, FEAT, 1);

    // K3: U_o = F0 @ M_o^T  (bilinear trick)  M=2048 N=256(j) K=256(i)
    //     M_o[j,i] = W_out[j*512 + i*2 + o]  ->  sK=2, sN=512, base=W_out+o
    sgemm_kernel<false, false><<<dim3(FEAT / BN, BATCH / BM, 2), 256>>>(
        F0, F0, W_out, W_out + 1, nullptr, nullptr, U0, U1,
        BATCH, FEAT, FEAT, 2, 512);

    // K4: out[b,o] = b_out[o] + <F1[b,:], U_o[b,:]>
    reduce_out_kernel<<<(BATCH * 32 + 255) / 256, 256>>>(F1, U0, U1, b_out, out);
}

// round 2
// speedup vs baseline: 1.8473x; 1.8473x over previous
#include <cuda_runtime.h>
#include <cuda_bf16.h>
#include <cstdint>

// ---------------------------------------------------------------------------
// B=2048, IN_DIM=1024, HID=512, FEAT=256, OUT=2
//   K1: H_z = relu(x_z @ W_feat + b_feat)          [2048,512]
//   K2: F_z = H_z @ W_br_z + b_br_z                [2048,256]
//   K3: U_o = F0 @ M_o^T  (bilinear kron trick)    [2048,256]
//   K4: out[b,o] = b_out[o] + <F1[b,:], U_o[b,:]>
// All GEMMs run on tensor cores (mma.sync m16n8k16 bf16) with a 2-term
// bf16 split (hi+lo) and 3 MMAs per tile: hi*hi + hi*lo + lo*hi -> fp32 acc.
// ---------------------------------------------------------------------------

#define BATCH   2048
#define IN_DIM  1024
#define HID     512
#define FEAT    256

// ------------------------- scratch (no cudaMalloc) -------------------------
__device__ __align__(16) __nv_bfloat16 g_Xhi[2 * BATCH * IN_DIM];
__device__ __align__(16) __nv_bfloat16 g_Xlo[2 * BATCH * IN_DIM];
__device__ __align__(16) __nv_bfloat16 g_Wfhi[IN_DIM * HID];
__device__ __align__(16) __nv_bfloat16 g_Wflo[IN_DIM * HID];
__device__ __align__(16) __nv_bfloat16 g_Wbhi[2 * HID * FEAT];
__device__ __align__(16) __nv_bfloat16 g_Wblo[2 * HID * FEAT];
__device__ __align__(16) __nv_bfloat16 g_Wohi[2 * FEAT * FEAT];
__device__ __align__(16) __nv_bfloat16 g_Wolo[2 * FEAT * FEAT];
__device__ __align__(16) float         g_H[2 * BATCH * HID];
__device__ __align__(16) __nv_bfloat16 g_Hhi[2 * BATCH * HID];
__device__ __align__(16) __nv_bfloat16 g_Hlo[2 * BATCH * HID];
__device__ __align__(16) float         g_F[2 * BATCH * FEAT];
__device__ __align__(16) __nv_bfloat16 g_F0hi[BATCH * FEAT];
__device__ __align__(16) __nv_bfloat16 g_F0lo[BATCH * FEAT];
__device__ __align__(16) float         g_U[2 * BATCH * FEAT];

// --------------------------- helpers ---------------------------------------
__device__ __forceinline__ void mma16816(float* c, const uint32_t* a, const uint32_t* b)
{
    asm volatile(
        "mma.sync.aligned.m16n8k16.row.col.f32.bf16.bf16.f32 "
        "{%0,%1,%2,%3}, {%4,%5,%6,%7}, {%8,%9}, {%0,%1,%2,%3};\n"
        : "+f"(c[0]), "+f"(c[1]), "+f"(c[2]), "+f"(c[3])
        : "r"(a[0]), "r"(a[1]), "r"(a[2]), "r"(a[3]), "r"(b[0]), "r"(b[1]));
}

// ------------------------- split-bf16 GEMM ---------------------------------
// C[M,N] (fp32) = A[M,K] @ B[K,N] (+bias, +relu), A/B given as bf16 hi/lo.
// CTA tile: 128 x BN, BK=16. blockIdx.z picks between two problem instances.
template <int BN, int WARPS_N, bool RELU, bool HAS_BIAS>
__global__ void __launch_bounds__(256, 1)
bgemm_kernel(const __nv_bfloat16* __restrict__ Ahi0, const __nv_bfloat16* __restrict__ Alo0,
             const __nv_bfloat16* __restrict__ Ahi1, const __nv_bfloat16* __restrict__ Alo1,
             const __nv_bfloat16* __restrict__ Bhi0, const __nv_bfloat16* __restrict__ Blo0,
             const __nv_bfloat16* __restrict__ Bhi1, const __nv_bfloat16* __restrict__ Blo1,
             const float* __restrict__ bias0, const float* __restrict__ bias1,
             float* __restrict__ C0, float* __restrict__ C1,
             int M, int N, int K)
{
    constexpr int BM = 128, BK = 16, KPAD = 20;
    constexpr int WARPS_M = 8 / WARPS_N;
    constexpr int WT_M = BM / WARPS_M;       // 64 or 32
    constexpr int WT_N = BN / WARPS_N;       // 32
    constexpr int MI = WT_M / 16;            // 4 or 2
    constexpr int NI = WT_N / 8;             // 4
    constexpr int AW = 4;                    // A 32-bit words / thread / array
    constexpr int BW = BN / 32;              // B 32-bit words / thread / array
    constexpr int BLOG = (BN == 128) ? 6 : 5;
    constexpr int BKSTEP = 256 >> BLOG;      // k-rows covered per pass

    const __nv_bfloat16* Ahi = blockIdx.z ? Ahi1 : Ahi0;
    const __nv_bfloat16* Alo = blockIdx.z ? Alo1 : Alo0;
    const __nv_bfloat16* Bhi = blockIdx.z ? Bhi1 : Bhi0;
    const __nv_bfloat16* Blo = blockIdx.z ? Blo1 : Blo0;
    const float* bias = blockIdx.z ? bias1 : bias0;
    float* C = blockIdx.z ? C1 : C0;

    __shared__ __nv_bfloat16 As[2][2][BM * KPAD];   // [buf][hi/lo], As[m][k]
    __shared__ __nv_bfloat16 Bs[2][2][BN * KPAD];   // [buf][hi/lo], Bs[n][k]

    const int tid = threadIdx.x;
    const int rowBlock = blockIdx.y * BM;
    const int colBlock = blockIdx.x * BN;

    // gmem->reg staging maps
    const int aRow0 = tid >> 3;                // 0..31 (+32 per pass)
    const int aCol  = tid & 7;                 // word col (2 halves)
    const int bK0   = tid >> BLOG;
    const int bCol  = tid & ((BN / 2) - 1);

    uint32_t sAhi[AW], sAlo[AW], sBhi[BW], sBlo[BW];

    auto load_gmem = [&](int kt) {
        #pragma unroll
        for (int i = 0; i < AW; i++) {
            size_t off = (size_t)(rowBlock + aRow0 + i * 32) * K + kt + aCol * 2;
            sAhi[i] = *reinterpret_cast<const uint32_t*>(Ahi + off);
            sAlo[i] = *reinterpret_cast<const uint32_t*>(Alo + off);
        }
        #pragma unroll
        for (int i = 0; i < BW; i++) {
            size_t off = (size_t)(kt + bK0 + i * BKSTEP) * N + colBlock + bCol * 2;
            sBhi[i] = *reinterpret_cast<const uint32_t*>(Bhi + off);
            sBlo[i] = *reinterpret_cast<const uint32_t*>(Blo + off);
        }
    };

    auto store_smem = [&](int buf) {
        #pragma unroll
        for (int i = 0; i < AW; i++) {
            int idx = (aRow0 + i * 32) * KPAD + aCol * 2;
            *reinterpret_cast<uint32_t*>(&As[buf][0][idx]) = sAhi[i];
            *reinterpret_cast<uint32_t*>(&As[buf][1][idx]) = sAlo[i];
        }
        #pragma unroll
        for (int i = 0; i < BW; i++) {
            int k = bK0 + i * BKSTEP;
            __nv_bfloat162 vh = *reinterpret_cast<__nv_bfloat162*>(&sBhi[i]);
            __nv_bfloat162 vl = *reinterpret_cast<__nv_bfloat162*>(&sBlo[i]);
            Bs[buf][0][(bCol * 2    ) * KPAD + k] = vh.x;
            Bs[buf][0][(bCol * 2 + 1) * KPAD + k] = vh.y;
            Bs[buf][1][(bCol * 2    ) * KPAD + k] = vl.x;
            Bs[buf][1][(bCol * 2 + 1) * KPAD + k] = vl.y;
        }
    };

    const int warp = tid >> 5, lane = tid & 31;
    const int wm = warp / WARPS_N, wn = warp % WARPS_N;
    const int g = lane >> 2, kq = lane & 3;
    const int aBaseRow = wm * WT_M + g;
    const int bBaseN   = wn * WT_N + g;

    float acc[MI][NI][4];
    #pragma unroll
    for (int mi = 0; mi < MI; mi++)
        #pragma unroll
        for (int ni = 0; ni < NI; ni++)
            #pragma unroll
            for (int r = 0; r < 4; r++) acc[mi][ni][r] = 0.0f;

    const int T = K / BK;
    load_gmem(0);
    store_smem(0);
    __syncthreads();

    for (int t = 0; t < T; t++) {
        if (t + 1 < T) load_gmem((t + 1) * BK);
        const int cur = t & 1;

        uint32_t ah[MI][4], al[MI][4];
        #pragma unroll
        for (int mi = 0; mi < MI; mi++) {
            const __nv_bfloat16* pH = &As[cur][0][(aBaseRow + mi * 16) * KPAD + kq * 2];
            const __nv_bfloat16* pL = &As[cur][1][(aBaseRow + mi * 16) * KPAD + kq * 2];
            ah[mi][0] = *reinterpret_cast<const uint32_t*>(pH);
            ah[mi][1] = *reinterpret_cast<const uint32_t*>(pH + 8 * KPAD);
            ah[mi][2] = *reinterpret_cast<const uint32_t*>(pH + 8);
            ah[mi][3] = *reinterpret_cast<const uint32_t*>(pH + 8 * KPAD + 8);
            al[mi][0] = *reinterpret_cast<const uint32_t*>(pL);
            al[mi][1] = *reinterpret_cast<const uint32_t*>(pL + 8 * KPAD);
            al[mi][2] = *reinterpret_cast<const uint32_t*>(pL + 8);
            al[mi][3] = *reinterpret_cast<const uint32_t*>(pL + 8 * KPAD + 8);
        }
        uint32_t bh[NI][2], bl[NI][2];
        #pragma unroll
        for (int ni = 0; ni < NI; ni++) {
            const __nv_bfloat16* pH = &Bs[cur][0][(bBaseN + ni * 8) * KPAD + kq * 2];
            const __nv_bfloat16* pL = &Bs[cur][1][(bBaseN + ni * 8) * KPAD + kq * 2];
            bh[ni][0] = *reinterpret_cast<const uint32_t*>(pH);
            bh[ni][1] = *reinterpret_cast<const uint32_t*>(pH + 8);
            bl[ni][0] = *reinterpret_cast<const uint32_t*>(pL);
            bl[ni][1] = *reinterpret_cast<const uint32_t*>(pL + 8);
        }

        #pragma unroll
        for (int mi = 0; mi < MI; mi++)
            #pragma unroll
            for (int ni = 0; ni < NI; ni++) {
                mma16816(acc[mi][ni], ah[mi], bh[ni]);   // hi*hi
                mma16816(acc[mi][ni], ah[mi], bl[ni]);   // hi*lo
                mma16816(acc[mi][ni], al[mi], bh[ni]);   // lo*hi
            }

        if (t + 1 < T) store_smem((t + 1) & 1);
        __syncthreads();
    }

    // epilogue
    #pragma unroll
    for (int mi = 0; mi < MI; mi++) {
        int row0 = rowBlock + wm * WT_M + mi * 16 + g;
        #pragma unroll
        for (int ni = 0; ni < NI; ni++) {
            int col = colBlock + wn * WT_N + ni * 8 + kq * 2;
            float b0v = 0.0f, b1v = 0.0f;
            if (HAS_BIAS) { b0v = bias[col]; b1v = bias[col + 1]; }
            float v0 = acc[mi][ni][0] + b0v;
            float v1 = acc[mi][ni][1] + b1v;
            float v2 = acc[mi][ni][2] + b0v;
            float v3 = acc[mi][ni][3] + b1v;
            if (RELU) {
                v0 = fmaxf(v0, 0.0f); v1 = fmaxf(v1, 0.0f);
                v2 = fmaxf(v2, 0.0f); v3 = fmaxf(v3, 0.0f);
            }
            *reinterpret_cast<float2*>(&C[(size_t)row0 * N + col])       = make_float2(v0, v1);
            *reinterpret_cast<float2*>(&C[(size_t)(row0 + 8) * N + col]) = make_float2(v2, v3);
        }
    }
}

// ------------------------- converters --------------------------------------
__global__ void conv_pair_kernel(const float* __restrict__ src,
                                 __nv_bfloat16* __restrict__ hi,
                                 __nv_bfloat16* __restrict__ lo, int n4)
{
    int i = blockIdx.x * blockDim.x + threadIdx.x;
    if (i >= n4) return;
    float4 v = reinterpret_cast<const float4*>(src)[i];
    __nv_bfloat16 h0 = __float2bfloat16(v.x), h1 = __float2bfloat16(v.y);
    __nv_bfloat16 h2 = __float2bfloat16(v.z), h3 = __float2bfloat16(v.w);
    __nv_bfloat16 l0 = __float2bfloat16(v.x - __bfloat162float(h0));
    __nv_bfloat16 l1 = __float2bfloat16(v.y - __bfloat162float(h1));
    __nv_bfloat16 l2 = __float2bfloat16(v.z - __bfloat162float(h2));
    __nv_bfloat16 l3 = __float2bfloat16(v.w - __bfloat162float(h3));
    __nv_bfloat162* hp = reinterpret_cast<__nv_bfloat162*>(hi) + (size_t)i * 2;
    __nv_bfloat162* lp = reinterpret_cast<__nv_bfloat162*>(lo) + (size_t)i * 2;
    hp[0] = __halves2bfloat162(h0, h1);
    hp[1] = __halves2bfloat162(h2, h3);
    lp[0] = __halves2bfloat162(l0, l1);
    lp[1] = __halves2bfloat162(l2, l3);
}

// Rearranged W_out views: dst_o[i*FEAT + j] = W_out[(j*FEAT + i)*2 + o]
__global__ void conv_wout_kernel(const float* __restrict__ W,
                                 __nv_bfloat16* __restrict__ hi,
                                 __nv_bfloat16* __restrict__ lo)
{
    int idx = blockIdx.x * blockDim.x + threadIdx.x;   // 0 .. 2*FEAT*FEAT-1
    if (idx >= 2 * FEAT * FEAT) return;
    int o = idx >> 16;
    int r = idx & (FEAT * FEAT - 1);
    int i = r >> 8, j = r & (FEAT - 1);
    float v = W[((size_t)j * FEAT + i) * 2 + o];
    __nv_bfloat16 h = __float2bfloat16(v);
    hi[idx] = h;
    lo[idx] = __float2bfloat16(v - __bfloat162float(h));
}

// ------------------------- final reduce ------------------------------------
__global__ void __launch_bounds__(256)
reduce_out_kernel(const float* __restrict__ F1,
                  const float* __restrict__ U0,
                  const float* __restrict__ U1,
                  const float* __restrict__ b_out,
                  float* __restrict__ out)
{
    int warp = (blockIdx.x * blockDim.x + threadIdx.x) >> 5;
    int lane = threadIdx.x & 31;
    if (warp >= BATCH) return;

    const float* f  = F1 + (size_t)warp * FEAT;
    const float* u0 = U0 + (size_t)warp * FEAT;
    const float* u1 = U1 + (size_t)warp * FEAT;

    float s0 = 0.0f, s1 = 0.0f;
    #pragma unroll
    for (int j = lane; j < FEAT; j += 32) {
        float fv = f[j];
        s0 = fmaf(fv, u0[j], s0);
        s1 = fmaf(fv, u1[j], s1);
    }
    #pragma unroll
    for (int off = 16; off; off >>= 1) {
        s0 += __shfl_down_sync(0xFFFFFFFFu, s0, off);
        s1 += __shfl_down_sync(0xFFFFFFFFu, s1, off);
    }
    if (lane == 0) {
        out[warp * 2 + 0] = s0 + b_out[0];
        out[warp * 2 + 1] = s1 + b_out[1];
    }
}

// ------------------------- launch ------------------------------------------
extern "C" void kernel_launch(void* const* d_in, const int* in_sizes, int n_in,
                              void* d_out, int out_size)
{
    const float* x0     = (const float*)d_in[0];
    const float* x1     = (const float*)d_in[1];
    const float* W_feat = (const float*)d_in[2];
    const float* b_feat = (const float*)d_in[3];
    const float* W_br0  = (const float*)d_in[4];
    const float* b_br0  = (const float*)d_in[5];
    const float* W_br1  = (const float*)d_in[6];
    const float* b_br1  = (const float*)d_in[7];
    const float* W_out  = (const float*)d_in[8];
    const float* b_out  = (const float*)d_in[9];
    float*       out    = (float*)d_out;

    __nv_bfloat16 *Xhi, *Xlo, *Wfhi, *Wflo, *Wbhi, *Wblo, *Wohi, *Wolo;
    __nv_bfloat16 *Hhi, *Hlo, *F0hi, *F0lo;
    float *H, *F, *U;
    cudaGetSymbolAddress((void**)&Xhi, g_Xhi);   cudaGetSymbolAddress((void**)&Xlo, g_Xlo);
    cudaGetSymbolAddress((void**)&Wfhi, g_Wfhi); cudaGetSymbolAddress((void**)&Wflo, g_Wflo);
    cudaGetSymbolAddress((void**)&Wbhi, g_Wbhi); cudaGetSymbolAddress((void**)&Wblo, g_Wblo);
    cudaGetSymbolAddress((void**)&Wohi, g_Wohi); cudaGetSymbolAddress((void**)&Wolo, g_Wolo);
    cudaGetSymbolAddress((void**)&Hhi, g_Hhi);   cudaGetSymbolAddress((void**)&Hlo, g_Hlo);
    cudaGetSymbolAddress((void**)&F0hi, g_F0hi); cudaGetSymbolAddress((void**)&F0lo, g_F0lo);
    cudaGetSymbolAddress((void**)&H, g_H);
    cudaGetSymbolAddress((void**)&F, g_F);
    cudaGetSymbolAddress((void**)&U, g_U);

    float* H0 = H;  float* H1 = H + (size_t)BATCH * HID;
    float* F0 = F;  float* F1 = F + (size_t)BATCH * FEAT;
    float* U0 = U;  float* U1 = U + (size_t)BATCH * FEAT;

    const int XN4 = BATCH * IN_DIM / 4;
    conv_pair_kernel<<<(XN4 + 255) / 256, 256>>>(x0, Xhi, Xlo, XN4);
    conv_pair_kernel<<<(XN4 + 255) / 256, 256>>>(x1, Xhi + (size_t)BATCH * IN_DIM,
                                                 Xlo + (size_t)BATCH * IN_DIM, XN4);
    const int WFN4 = IN_DIM * HID / 4;
    conv_pair_kernel<<<(WFN4 + 255) / 256, 256>>>(W_feat, Wfhi, Wflo, WFN4);
    const int WBN4 = HID * FEAT / 4;
    conv_pair_kernel<<<(WBN4 + 255) / 256, 256>>>(W_br0, Wbhi, Wblo, WBN4);
    conv_pair_kernel<<<(WBN4 + 255) / 256, 256>>>(W_br1, Wbhi + HID * FEAT,
                                                  Wblo + HID * FEAT, WBN4);
    conv_wout_kernel<<<(2 * FEAT * FEAT + 255) / 256, 256>>>(W_out, Wohi, Wolo);

    // K1: H_z = relu(x_z @ W_feat + b_feat)    M=2048 N=512 K=1024
    bgemm_kernel<128, 4, true, true><<<dim3(HID / 128, BATCH / 128, 2), 256>>>(
        Xhi, Xlo, Xhi + (size_t)BATCH * IN_DIM, Xlo + (size_t)BATCH * IN_DIM,
        Wfhi, Wflo, Wfhi, Wflo, b_feat, b_feat, H0, H1,
        BATCH, HID, IN_DIM);

    const int HN4 = 2 * BATCH * HID / 4;
    conv_pair_kernel<<<(HN4 + 255) / 256, 256>>>(H, Hhi, Hlo, HN4);

    // K2: F_z = H_z @ W_br_z + b_br_z          M=2048 N=256 K=512
    bgemm_kernel<64, 2, false, true><<<dim3(FEAT / 64, BATCH / 128, 2), 256>>>(
        Hhi, Hlo, Hhi + (size_t)BATCH * HID, Hlo + (size_t)BATCH * HID,
        Wbhi, Wblo, Wbhi + HID * FEAT, Wblo + HID * FEAT,
        b_br0, b_br1, F0, F1,
        BATCH, FEAT, HID);

    const int FN4 = BATCH * FEAT / 4;
    conv_pair_kernel<<<(FN4 + 255) / 256, 256>>>(F0, F0hi, F0lo, FN4);

    // K3: U_o = F0 @ M_o^T                     M=2048 N=256 K=256
    bgemm_kernel<64, 2, false, false><<<dim3(FEAT / 64, BATCH / 128, 2), 256>>>(
        F0hi, F0lo, F0hi, F0lo,
        Wohi, Wolo, Wohi + FEAT * FEAT, Wolo + FEAT * FEAT,
        nullptr, nullptr, U0, U1,
        BATCH, FEAT, FEAT);

    // K4
    reduce_out_kernel<<<(BATCH * 32 + 255) / 256, 256>>>(F1, U0, U1, b_out, out);
}

// round 4
// speedup vs baseline: 2.8040x; 1.5178x over previous
#include <cuda_runtime.h>
#include <cuda_bf16.h>
#include <cstdint>

#define BATCH   2048
#define IN_DIM  1024
#define HID     512
#define FEAT    256

// ---------------------------------------------------------------------------
// helpers
// ---------------------------------------------------------------------------
__device__ __forceinline__ uint32_t smem_u32(const void* p) {
    uint32_t a;
    asm("{ .reg .u64 t; cvta.to.shared.u64 t, %1; cvt.u32.u64 %0, t; }"
        : "=r"(a) : "l"(p));
    return a;
}

__device__ __forceinline__ void mma16816(float* c, const uint32_t* a, const uint32_t* b)
{
    asm volatile(
        "mma.sync.aligned.m16n8k16.row.col.f32.bf16.bf16.f32 "
        "{%0,%1,%2,%3}, {%4,%5,%6,%7}, {%8,%9}, {%0,%1,%2,%3};\n"
        : "+f"(c[0]), "+f"(c[1]), "+f"(c[2]), "+f"(c[3])
        : "r"(a[0]), "r"(a[1]), "r"(a[2]), "r"(a[3]), "r"(b[0]), "r"(b[1]));
}

#define LDSM4(r0, r1, r2, r3, addr)                                            \
    asm volatile("ldmatrix.sync.aligned.m8n8.x4.shared.b16 {%0,%1,%2,%3}, [%4];" \
        : "=r"(r0), "=r"(r1), "=r"(r2), "=r"(r3) : "r"(addr))

#define CP16(dst, src)                                                         \
    asm volatile("cp.async.cg.shared.global [%0], [%1], 16;"                   \
        :: "r"(dst), "l"(src))
#define CP_COMMIT() asm volatile("cp.async.commit_group;" ::: "memory")
#define CP_WAIT1()  asm volatile("cp.async.wait_group 1;" ::: "memory")
#define CP_WAIT0()  asm volatile("cp.async.wait_group 0;" ::: "memory")

// ---------------------------- scratch ---------------------------------------
__device__ __align__(16) __nv_bfloat16 g_Xhi[2 * BATCH * IN_DIM];
__device__ __align__(16) __nv_bfloat16 g_Xlo[2 * BATCH * IN_DIM];
__device__ __align__(16) __nv_bfloat16 g_Wfhi[HID * IN_DIM];      // [N=512][K=1024]
__device__ __align__(16) __nv_bfloat16 g_Wflo[HID * IN_DIM];
__device__ __align__(16) __nv_bfloat16 g_Wbhi[2 * FEAT * HID];    // [z][N=256][K=512]
__device__ __align__(16) __nv_bfloat16 g_Wblo[2 * FEAT * HID];
__device__ __align__(16) __nv_bfloat16 g_Wohi[2 * FEAT * FEAT];   // [o][j][i]
__device__ __align__(16) __nv_bfloat16 g_Wolo[2 * FEAT * FEAT];
__device__ __align__(16) __nv_bfloat16 g_Hhi[2 * BATCH * HID];
__device__ __align__(16) __nv_bfloat16 g_Hlo[2 * BATCH * HID];
__device__ __align__(16) __nv_bfloat16 g_F0hi[BATCH * FEAT];
__device__ __align__(16) __nv_bfloat16 g_F0lo[BATCH * FEAT];
__device__ __align__(16) float         g_F1[BATCH * FEAT];
__device__ __align__(16) float         g_U[2 * BATCH * FEAT];

// ---------------------------------------------------------------------------
// Split-bf16 mma.sync GEMM.
//   A[M,KK] row-major bf16 hi/lo; B[NOUT,KK] row-major bf16 hi/lo (pre-transposed).
//   acc fp32 = Ahi*Bhi + Ahi*Blo + Alo*Bhi over full K.
// Smem tiles: rows of 64B (BK=32 halves) padded to 80B; cp.async double buffer.
// MODE 0: K1 (bias+relu, split-bf16 out, z offsets A and O)
// MODE 1: K2 (bias; z=0 -> split-bf16 F0, z=1 -> fp32 F1)
// MODE 2: K3 (no bias, fp32 out U_z)
// ---------------------------------------------------------------------------
template <int BM, int BN, int THREADS, int KK, int NOUT, int MODE>
__global__ void __launch_bounds__(THREADS, 1)
gemm_mma(const __nv_bfloat16* __restrict__ Ahi, const __nv_bfloat16* __restrict__ Alo,
         const __nv_bfloat16* __restrict__ Bhi, const __nv_bfloat16* __restrict__ Blo,
         const float* __restrict__ bias0, const float* __restrict__ bias1,
         __nv_bfloat16* __restrict__ Ohi, __nv_bfloat16* __restrict__ Olo,
         float* __restrict__ Ofa, float* __restrict__ Ofb)
{
    constexpr int BK   = 32;                  // halves per stage
    constexpr int ROWB = 80;                  // 64B data + 16B pad
    constexpr int T    = KK / BK;
    constexpr int WARPS = THREADS / 32;
    constexpr int WN_W = (BN == 128) ? 4 : 2;
    constexpr int WM_W = WARPS / WN_W;
    constexpr int WTM  = BM / WM_W;           // 64 / 32
    constexpr int WTN  = BN / WN_W;           // 32
    constexpr int MI   = WTM / 16;            // 4 / 2
    constexpr int NI   = WTN / 8;             // 4
    constexpr int STAGE = (2 * BM + 2 * BN) * ROWB;
    constexpr size_t AZ = (MODE == 0) ? (size_t)BATCH * IN_DIM
                         : (MODE == 1) ? (size_t)BATCH * HID : 0;
    constexpr size_t BZ = (MODE == 0) ? 0
                         : (MODE == 1) ? (size_t)FEAT * HID : (size_t)FEAT * FEAT;
    constexpr size_t OZ = (size_t)BATCH * NOUT;

    extern __shared__ char dsm[];
    const uint32_t sbase = smem_u32(dsm);

    const int tid  = threadIdx.x;
    const int lane = tid & 31;
    const int warp = tid >> 5;
    const int wm = warp / WN_W, wn = warp % WN_W;
    const int z = blockIdx.z;
    const int rowBlock = blockIdx.y * BM;
    const int colBlock = blockIdx.x * BN;

    Ahi += (size_t)z * AZ;  Alo += (size_t)z * AZ;
    Bhi += (size_t)z * BZ;  Blo += (size_t)z * BZ;
    const float* bias = z ? bias1 : bias0;

    // cp.async staging of one stage (Ahi|Alo|Bhi|Blo)
    auto stage = [&](int t) {
        const int kt = t * BK;
        const uint32_t buf = sbase + (t & 1) * STAGE;
        #pragma unroll
        for (int i = 0; i < BM * 4 / THREADS; i++) {
            int slot = tid + i * THREADS;
            int row = slot >> 2, ch = slot & 3;
            uint32_t d = buf + row * ROWB + ch * 16;
            CP16(d, Ahi + (size_t)(rowBlock + row) * KK + kt + ch * 8);
            CP16(d + BM * ROWB, Alo + (size_t)(rowBlock + row) * KK + kt + ch * 8);
        }
        #pragma unroll
        for (int i = 0; i < BN * 4 / THREADS; i++) {
            int slot = tid + i * THREADS;
            int row = slot >> 2, ch = slot & 3;
            uint32_t d = buf + 2 * BM * ROWB + row * ROWB + ch * 16;
            CP16(d, Bhi + (size_t)(colBlock + row) * KK + kt + ch * 8);
            CP16(d + BN * ROWB, Blo + (size_t)(colBlock + row) * KK + kt + ch * 8);
        }
        CP_COMMIT();
    };

    float acc[MI][NI][4];
    #pragma unroll
    for (int mi = 0; mi < MI; mi++)
        #pragma unroll
        for (int ni = 0; ni < NI; ni++)
            #pragma unroll
            for (int r = 0; r < 4; r++) acc[mi][ni][r] = 0.0f;

    // ldmatrix per-lane address components (within a stage buffer)
    const uint32_t aOff = (uint32_t)((wm * WTM + (lane & 15)) * ROWB + (lane >> 4) * 16);
    const uint32_t bOff = (uint32_t)((wn * WTN + ((lane >> 4) << 3) + (lane & 7)) * ROWB
                                     + ((lane >> 3) & 1) * 16);

    stage(0);

    #pragma unroll 1
    for (int t = 0; t < T; t++) {
        if (t + 1 < T) stage(t + 1);
        if (t + 1 < T) { CP_WAIT1(); } else { CP_WAIT0(); }
        __syncthreads();

        const uint32_t buf  = sbase + (t & 1) * STAGE;
        const uint32_t aHiB = buf + aOff;
        const uint32_t aLoB = aHiB + BM * ROWB;
        const uint32_t bHiB = buf + 2 * BM * ROWB + bOff;
        const uint32_t bLoB = bHiB + BN * ROWB;

        #pragma unroll
        for (int ks = 0; ks < 2; ks++) {
            const uint32_t ko = ks * 32;   // 16 halves = 32B
            uint32_t ah[MI][4], al[MI][4];
            #pragma unroll
            for (int mi = 0; mi < MI; mi++) {
                LDSM4(ah[mi][0], ah[mi][1], ah[mi][2], ah[mi][3],
                      aHiB + mi * 16 * ROWB + ko);
                LDSM4(al[mi][0], al[mi][1], al[mi][2], al[mi][3],
                      aLoB + mi * 16 * ROWB + ko);
            }
            uint32_t bh[NI][2], bl[NI][2];
            #pragma unroll
            for (int np = 0; np < NI / 2; np++) {
                LDSM4(bh[np * 2][0], bh[np * 2][1], bh[np * 2 + 1][0], bh[np * 2 + 1][1],
                      bHiB + np * 16 * ROWB + ko);
                LDSM4(bl[np * 2][0], bl[np * 2][1], bl[np * 2 + 1][0], bl[np * 2 + 1][1],
                      bLoB + np * 16 * ROWB + ko);
            }
            #pragma unroll
            for (int mi = 0; mi < MI; mi++)
                #pragma unroll
                for (int ni = 0; ni < NI; ni++) {
                    mma16816(acc[mi][ni], ah[mi], bh[ni]);
                    mma16816(acc[mi][ni], ah[mi], bl[ni]);
                    mma16816(acc[mi][ni], al[mi], bh[ni]);
                }
        }
        __syncthreads();
    }

    // ------------------------------ epilogue --------------------------------
    const int g  = lane >> 2;
    const int kq = lane & 3;
    #pragma unroll
    for (int mi = 0; mi < MI; mi++) {
        #pragma unroll
        for (int half = 0; half < 2; half++) {
            const int grow = rowBlock + wm * WTM + mi * 16 + half * 8 + g;
            #pragma unroll
            for (int ni = 0; ni < NI; ni++) {
                const int gc = colBlock + wn * WTN + ni * 8 + kq * 2;
                float v0 = acc[mi][ni][half * 2 + 0];
                float v1 = acc[mi][ni][half * 2 + 1];
                if (MODE != 2) { v0 += bias[gc]; v1 += bias[gc + 1]; }
                if (MODE == 0) { v0 = fmaxf(v0, 0.0f); v1 = fmaxf(v1, 0.0f); }
                const size_t base = (size_t)grow * NOUT + gc;

                if (MODE == 0 || (MODE == 1 && z == 0)) {
                    __nv_bfloat16 h0 = __float2bfloat16(v0);
                    __nv_bfloat16 h1 = __float2bfloat16(v1);
                    __nv_bfloat16 l0 = __float2bfloat16(v0 - __bfloat162float(h0));
                    __nv_bfloat16 l1 = __float2bfloat16(v1 - __bfloat162float(h1));
                    __nv_bfloat16* oh = Ohi;
                    __nv_bfloat16* ol = Olo;
                    if (MODE == 0) { oh += (size_t)z * OZ; ol += (size_t)z * OZ; }
                    *reinterpret_cast<__nv_bfloat162*>(oh + base) = __halves2bfloat162(h0, h1);
                    *reinterpret_cast<__nv_bfloat162*>(ol + base) = __halves2bfloat162(l0, l1);
                } else {
                    float* of = (MODE == 1) ? Ofa : (z ? Ofb : Ofa);
                    *reinterpret_cast<float2*>(of + base) = make_float2(v0, v1);
                }
            }
        }
    }
}

// ---------------------------- converters ------------------------------------
__global__ void conv_pair_kernel(const float* __restrict__ src,
                                 __nv_bfloat16* __restrict__ hi,
                                 __nv_bfloat16* __restrict__ lo, int n4)
{
    int i = blockIdx.x * blockDim.x + threadIdx.x;
    if (i >= n4) return;
    float4 vv = reinterpret_cast<const float4*>(src)[i];
    float a[4] = {vv.x, vv.y, vv.z, vv.w};
    __nv_bfloat16 h[4], l[4];
    #pragma unroll
    for (int k = 0; k < 4; k++) {
        h[k] = __float2bfloat16(a[k]);
        l[k] = __float2bfloat16(a[k] - __bfloat162float(h[k]));
    }
    __nv_bfloat162* hp = reinterpret_cast<__nv_bfloat162*>(hi) + (size_t)i * 2;
    __nv_bfloat162* lp = reinterpret_cast<__nv_bfloat162*>(lo) + (size_t)i * 2;
    hp[0] = __halves2bfloat162(h[0], h[1]);
    hp[1] = __halves2bfloat162(h[2], h[3]);
    lp[0] = __halves2bfloat162(l[0], l[1]);
    lp[1] = __halves2bfloat162(l[2], l[3]);
}

// W [Krows, Ncols] fp32 -> Wt [Ncols, Krows] bf16 hi/lo
__global__ void transpose_split_kernel(const float* __restrict__ W0,
                                       const float* __restrict__ W1,
                                       __nv_bfloat16* __restrict__ hi,
                                       __nv_bfloat16* __restrict__ lo,
                                       int Krows, int Ncols)
{
    __shared__ float tile[32][33];
    const float* W = blockIdx.z ? W1 : W0;
    size_t zoff = (size_t)blockIdx.z * Krows * Ncols;
    int n0 = blockIdx.x * 32, k0 = blockIdx.y * 32;
    int tx = threadIdx.x, ty = threadIdx.y;   // 32 x 8
    #pragma unroll
    for (int i = 0; i < 32; i += 8)
        tile[ty + i][tx] = W[(size_t)(k0 + ty + i) * Ncols + n0 + tx];
    __syncthreads();
    #pragma unroll
    for (int i = 0; i < 32; i += 8) {
        float vv = tile[tx][ty + i];
        __nv_bfloat16 h = __float2bfloat16(vv);
        size_t o = zoff + (size_t)(n0 + ty + i) * Krows + k0 + tx;
        hi[o] = h;
        lo[o] = __float2bfloat16(vv - __bfloat162float(h));
    }
}

// Wo[o][j*FEAT + i] = split(W_out[(j*FEAT + i)*2 + o])
__global__ void conv_wout_kernel(const float* __restrict__ W,
                                 __nv_bfloat16* __restrict__ hi,
                                 __nv_bfloat16* __restrict__ lo)
{
    int idx = blockIdx.x * blockDim.x + threadIdx.x;
    if (idx >= 2 * FEAT * FEAT) return;
    int o = idx >> 16;
    int r = idx & (FEAT * FEAT - 1);
    float vv = W[(size_t)r * 2 + o];
    __nv_bfloat16 h = __float2bfloat16(vv);
    hi[idx] = h;
    lo[idx] = __float2bfloat16(vv - __bfloat162float(h));
}

// ---------------------------- final reduce ----------------------------------
__global__ void __launch_bounds__(256)
reduce_out_kernel(const float* __restrict__ F1,
                  const float* __restrict__ U0,
                  const float* __restrict__ U1,
                  const float* __restrict__ b_out,
                  float* __restrict__ out)
{
    int warp = (blockIdx.x * blockDim.x + threadIdx.x) >> 5;
    int lane = threadIdx.x & 31;
    if (warp >= BATCH) return;

    const float4* f  = reinterpret_cast<const float4*>(F1 + (size_t)warp * FEAT) + lane * 2;
    const float4* u0 = reinterpret_cast<const float4*>(U0 + (size_t)warp * FEAT) + lane * 2;
    const float4* u1 = reinterpret_cast<const float4*>(U1 + (size_t)warp * FEAT) + lane * 2;

    float s0 = 0.0f, s1 = 0.0f;
    #pragma unroll
    for (int q = 0; q < 2; q++) {
        float4 fv = f[q], a = u0[q], c = u1[q];
        s0 = fmaf(fv.x, a.x, fmaf(fv.y, a.y, fmaf(fv.z, a.z, fmaf(fv.w, a.w, s0))));
        s1 = fmaf(fv.x, c.x, fmaf(fv.y, c.y, fmaf(fv.z, c.z, fmaf(fv.w, c.w, s1))));
    }
    #pragma unroll
    for (int off = 16; off; off >>= 1) {
        s0 += __shfl_down_sync(0xFFFFFFFFu, s0, off);
        s1 += __shfl_down_sync(0xFFFFFFFFu, s1, off);
    }
    if (lane == 0) {
        out[warp * 2 + 0] = s0 + b_out[0];
        out[warp * 2 + 1] = s1 + b_out[1];
    }
}

// ---------------------------- launch ----------------------------------------
extern "C" void kernel_launch(void* const* d_in, const int* in_sizes, int n_in,
                              void* d_out, int out_size)
{
    const float* x0     = (const float*)d_in[0];
    const float* x1     = (const float*)d_in[1];
    const float* W_feat = (const float*)d_in[2];
    const float* b_feat = (const float*)d_in[3];
    const float* W_br0  = (const float*)d_in[4];
    const float* b_br0  = (const float*)d_in[5];
    const float* W_br1  = (const float*)d_in[6];
    const float* b_br1  = (const float*)d_in[7];
    const float* W_out  = (const float*)d_in[8];
    const float* b_out  = (const float*)d_in[9];
    float*       out    = (float*)d_out;

    __nv_bfloat16 *Xhi, *Xlo, *Wfhi, *Wflo, *Wbhi, *Wblo, *Wohi, *Wolo;
    __nv_bfloat16 *Hhi, *Hlo, *F0hi, *F0lo;
    float *F1, *U;
    cudaGetSymbolAddress((void**)&Xhi, g_Xhi);   cudaGetSymbolAddress((void**)&Xlo, g_Xlo);
    cudaGetSymbolAddress((void**)&Wfhi, g_Wfhi); cudaGetSymbolAddress((void**)&Wflo, g_Wflo);
    cudaGetSymbolAddress((void**)&Wbhi, g_Wbhi); cudaGetSymbolAddress((void**)&Wblo, g_Wblo);
    cudaGetSymbolAddress((void**)&Wohi, g_Wohi); cudaGetSymbolAddress((void**)&Wolo, g_Wolo);
    cudaGetSymbolAddress((void**)&Hhi, g_Hhi);   cudaGetSymbolAddress((void**)&Hlo, g_Hlo);
    cudaGetSymbolAddress((void**)&F0hi, g_F0hi); cudaGetSymbolAddress((void**)&F0lo, g_F0lo);
    cudaGetSymbolAddress((void**)&F1, g_F1);
    cudaGetSymbolAddress((void**)&U, g_U);
    float* U0 = U;
    float* U1 = U + (size_t)BATCH * FEAT;

    // K1: BM=128 BN=128 THREADS=256 KK=1024 NOUT=512 MODE=0  (smem 80KB)
    // K2: BM=64  BN=64  THREADS=128 KK=512  NOUT=256 MODE=1  (smem 40KB)
    // K3: BM=64  BN=64  THREADS=128 KK=256  NOUT=256 MODE=2  (smem 40KB)
    constexpr int SM1 = 2 * (2 * 128 + 2 * 128) * 80;
    constexpr int SM2 = 2 * (2 * 64 + 2 * 64) * 80;
    cudaFuncSetAttribute((const void*)gemm_mma<128, 128, 256, 1024, 512, 0>,
                         cudaFuncAttributeMaxDynamicSharedMemorySize, SM1);
    cudaFuncSetAttribute((const void*)gemm_mma<64, 64, 128, 512, 256, 1>,
                         cudaFuncAttributeMaxDynamicSharedMemorySize, SM2);
    cudaFuncSetAttribute((const void*)gemm_mma<64, 64, 128, 256, 256, 2>,
                         cudaFuncAttributeMaxDynamicSharedMemorySize, SM2);

    // input conversions
    const int XN4 = BATCH * IN_DIM / 4;
    conv_pair_kernel<<<(XN4 + 255) / 256, 256>>>(x0, Xhi, Xlo, XN4);
    conv_pair_kernel<<<(XN4 + 255) / 256, 256>>>(x1, Xhi + (size_t)BATCH * IN_DIM,
                                                 Xlo + (size_t)BATCH * IN_DIM, XN4);
    transpose_split_kernel<<<dim3(HID / 32, IN_DIM / 32, 1), dim3(32, 8)>>>(
        W_feat, W_feat, Wfhi, Wflo, IN_DIM, HID);
    transpose_split_kernel<<<dim3(FEAT / 32, HID / 32, 2), dim3(32, 8)>>>(
        W_br0, W_br1, Wbhi, Wblo, HID, FEAT);
    conv_wout_kernel<<<(2 * FEAT * FEAT + 255) / 256, 256>>>(W_out, Wohi, Wolo);

    // K1: H_z = relu(x_z @ W_feat + b_feat) -> split bf16 (fused)
    gemm_mma<128, 128, 256, 1024, 512, 0>
        <<<dim3(HID / 128, BATCH / 128, 2), 256, SM1>>>(
        Xhi, Xlo, Wfhi, Wflo, b_feat, b_feat, Hhi, Hlo, nullptr, nullptr);

    // K2: F_z = H_z @ W_br_z + b_br_z  (z=0 -> split F0, z=1 -> fp32 F1)
    gemm_mma<64, 64, 128, 512, 256, 1>
        <<<dim3(FEAT / 64, BATCH / 64, 2), 128, SM2>>>(
        Hhi, Hlo, Wbhi, Wblo, b_br0, b_br1, F0hi, F0lo, F1, nullptr);

    // K3: U_o = F0 @ M_o^T -> fp32
    gemm_mma<64, 64, 128, 256, 256, 2>
        <<<dim3(FEAT / 64, BATCH / 64, 2), 128, SM2>>>(
        F0hi, F0lo, Wohi, Wolo, nullptr, nullptr, nullptr, nullptr, U0, U1);

    // K4
    reduce_out_kernel<<<(BATCH * 32 + 255) / 256, 256>>>(F1, U0, U1, b_out, out);
}

// round 5
// speedup vs baseline: 3.8292x; 1.3657x over previous
#include <cuda_runtime.h>
#include <cuda_fp16.h>
#include <cstdint>

#define BATCH   2048
#define IN_DIM  1024
#define HID     512
#define FEAT    256

// ---------------------------------------------------------------------------
// helpers
// ---------------------------------------------------------------------------
__device__ __forceinline__ uint32_t smem_u32(const void* p) {
    uint32_t a;
    asm("{ .reg .u64 t; cvta.to.shared.u64 t, %1; cvt.u32.u64 %0, t; }"
        : "=r"(a) : "l"(p));
    return a;
}

__device__ __forceinline__ void mma16816(float* c, const uint32_t* a, const uint32_t* b)
{
    asm volatile(
        "mma.sync.aligned.m16n8k16.row.col.f32.f16.f16.f32 "
        "{%0,%1,%2,%3}, {%4,%5,%6,%7}, {%8,%9}, {%0,%1,%2,%3};\n"
        : "+f"(c[0]), "+f"(c[1]), "+f"(c[2]), "+f"(c[3])
        : "r"(a[0]), "r"(a[1]), "r"(a[2]), "r"(a[3]), "r"(b[0]), "r"(b[1]));
}

#define LDSM4(r0, r1, r2, r3, addr)                                            \
    asm volatile("ldmatrix.sync.aligned.m8n8.x4.shared.b16 {%0,%1,%2,%3}, [%4];" \
        : "=r"(r0), "=r"(r1), "=r"(r2), "=r"(r3) : "r"(addr))

#define CP16(dst, src)                                                         \
    asm volatile("cp.async.cg.shared.global [%0], [%1], 16;"                   \
        :: "r"(dst), "l"(src))
#define CP_COMMIT() asm volatile("cp.async.commit_group;" ::: "memory")
#define CP_WAIT1()  asm volatile("cp.async.wait_group 1;" ::: "memory")
#define CP_WAIT0()  asm volatile("cp.async.wait_group 0;" ::: "memory")

// ---------------------------- scratch ---------------------------------------
__device__ __align__(16) __half g_Xhi[2 * BATCH * IN_DIM];
__device__ __align__(16) __half g_Xlo[2 * BATCH * IN_DIM];
__device__ __align__(16) __half g_Wfhi[HID * IN_DIM];       // [N=512][K=1024]
__device__ __align__(16) __half g_Wbhi[2 * FEAT * HID];     // [z][N=256][K=512]
__device__ __align__(16) __half g_Wohi[2 * FEAT * FEAT];    // [o][j][i]
__device__ __align__(16) __half g_Hhi[2 * BATCH * HID];
__device__ __align__(16) __half g_Hlo[2 * BATCH * HID];
__device__ __align__(16) __half g_F0hi[BATCH * FEAT];
__device__ __align__(16) __half g_F0lo[BATCH * FEAT];
__device__ __align__(16) float  g_F1[BATCH * FEAT];

// ---------------------------------------------------------------------------
// 2-term split-fp16 mma.sync GEMM.
//   A[M,KK] row-major fp16 hi/lo (exact to 22 mantissa bits);
//   B[NOUT,KK] row-major fp16 hi only (weights, pre-transposed).
//   acc fp32 = Ahi*Bhi + Alo*Bhi.
// MODE 0: K1 (bias+relu, split-fp16 out, z offsets A and O)
// MODE 1: K2 (bias; z=0 -> split-fp16 F0, z=1 -> fp32 F1)
// MODE 2: K3 (no bias, fused final dot: out[b,z] += <F1[b,:], Urow>)
// ---------------------------------------------------------------------------
template <int BM, int BN, int THREADS, int KK, int NOUT, int MODE>
__global__ void __launch_bounds__(THREADS, 1)
gemm_mma(const __half* __restrict__ Ahi, const __half* __restrict__ Alo,
         const __half* __restrict__ Bhi,
         const float* __restrict__ bias0, const float* __restrict__ bias1,
         __half* __restrict__ Ohi, __half* __restrict__ Olo,
         float* __restrict__ Ofa, float* __restrict__ Ofb)
{
    constexpr int BK   = 32;                  // halves per stage
    constexpr int ROWB = 80;                  // 64B data + 16B pad
    constexpr int T    = KK / BK;
    constexpr int WARPS = THREADS / 32;
    constexpr int WN_W = (BN == 128) ? 4 : 2;
    constexpr int WM_W = WARPS / WN_W;
    constexpr int WTM  = BM / WM_W;           // 64 / 32
    constexpr int WTN  = BN / WN_W;           // 32
    constexpr int MI   = WTM / 16;            // 4 / 2
    constexpr int NI   = WTN / 8;             // 4
    constexpr int STAGE = (2 * BM + BN) * ROWB;
    constexpr size_t AZ = (MODE == 0) ? (size_t)BATCH * IN_DIM
                         : (MODE == 1) ? (size_t)BATCH * HID : 0;
    constexpr size_t BZ = (MODE == 0) ? 0
                         : (MODE == 1) ? (size_t)FEAT * HID : (size_t)FEAT * FEAT;
    constexpr size_t OZ = (size_t)BATCH * NOUT;

    extern __shared__ char dsm[];
    const uint32_t sbase = smem_u32(dsm);

    const int tid  = threadIdx.x;
    const int lane = tid & 31;
    const int warp = tid >> 5;
    const int wm = warp / WN_W, wn = warp % WN_W;
    const int z = blockIdx.z;
    const int rowBlock = blockIdx.y * BM;
    const int colBlock = blockIdx.x * BN;

    Ahi += (size_t)z * AZ;  Alo += (size_t)z * AZ;
    Bhi += (size_t)z * BZ;
    const float* bias = z ? bias1 : bias0;

    auto stage = [&](int t) {
        const int kt = t * BK;
        const uint32_t buf = sbase + (t & 1) * STAGE;
        #pragma unroll
        for (int i = 0; i < BM * 4 / THREADS; i++) {
            int slot = tid + i * THREADS;
            int row = slot >> 2, ch = slot & 3;
            uint32_t d = buf + row * ROWB + ch * 16;
            CP16(d, Ahi + (size_t)(rowBlock + row) * KK + kt + ch * 8);
            CP16(d + BM * ROWB, Alo + (size_t)(rowBlock + row) * KK + kt + ch * 8);
        }
        #pragma unroll
        for (int i = 0; i < BN * 4 / THREADS; i++) {
            int slot = tid + i * THREADS;
            int row = slot >> 2, ch = slot & 3;
            CP16(buf + (2 * BM + row) * ROWB + ch * 16,
                 Bhi + (size_t)(colBlock + row) * KK + kt + ch * 8);
        }
        CP_COMMIT();
    };

    float acc[MI][NI][4];
    #pragma unroll
    for (int mi = 0; mi < MI; mi++)
        #pragma unroll
        for (int ni = 0; ni < NI; ni++)
            #pragma unroll
            for (int r = 0; r < 4; r++) acc[mi][ni][r] = 0.0f;

    const uint32_t aOff = (uint32_t)((wm * WTM + (lane & 15)) * ROWB + (lane >> 4) * 16);
    const uint32_t bOff = (uint32_t)((wn * WTN + ((lane >> 4) << 3) + (lane & 7)) * ROWB
                                     + ((lane >> 3) & 1) * 16);

    stage(0);

    #pragma unroll 1
    for (int t = 0; t < T; t++) {
        if (t + 1 < T) stage(t + 1);
        if (t + 1 < T) { CP_WAIT1(); } else { CP_WAIT0(); }
        __syncthreads();

        const uint32_t buf  = sbase + (t & 1) * STAGE;
        const uint32_t aHiB = buf + aOff;
        const uint32_t aLoB = aHiB + BM * ROWB;
        const uint32_t bHiB = buf + 2 * BM * ROWB + bOff;

        #pragma unroll
        for (int ks = 0; ks < 2; ks++) {
            const uint32_t ko = ks * 32;   // 16 halves = 32B
            uint32_t ah[MI][4], al[MI][4];
            #pragma unroll
            for (int mi = 0; mi < MI; mi++) {
                LDSM4(ah[mi][0], ah[mi][1], ah[mi][2], ah[mi][3],
                      aHiB + mi * 16 * ROWB + ko);
                LDSM4(al[mi][0], al[mi][1], al[mi][2], al[mi][3],
                      aLoB + mi * 16 * ROWB + ko);
            }
            uint32_t bh[NI][2];
            #pragma unroll
            for (int np = 0; np < NI / 2; np++) {
                LDSM4(bh[np * 2][0], bh[np * 2][1], bh[np * 2 + 1][0], bh[np * 2 + 1][1],
                      bHiB + np * 16 * ROWB + ko);
            }
            #pragma unroll
            for (int mi = 0; mi < MI; mi++)
                #pragma unroll
                for (int ni = 0; ni < NI; ni++) {
                    mma16816(acc[mi][ni], ah[mi], bh[ni]);
                    mma16816(acc[mi][ni], al[mi], bh[ni]);
                }
        }
        __syncthreads();
    }

    // ------------------------------ epilogue --------------------------------
    const int g  = lane >> 2;
    const int kq = lane & 3;
    #pragma unroll
    for (int mi = 0; mi < MI; mi++) {
        #pragma unroll
        for (int half = 0; half < 2; half++) {
            const int grow = rowBlock + wm * WTM + mi * 16 + half * 8 + g;
            if (MODE == 2) {
                // fused final dot: s = sum_cols U[grow,gc]*F1[grow,gc]
                const float* F1p = Ofa;
                float s = 0.0f;
                #pragma unroll
                for (int ni = 0; ni < NI; ni++) {
                    const int gc = colBlock + wn * WTN + ni * 8 + kq * 2;
                    float2 fv = *reinterpret_cast<const float2*>(
                        F1p + (size_t)grow * FEAT + gc);
                    s = fmaf(acc[mi][ni][half * 2 + 0], fv.x,
                        fmaf(acc[mi][ni][half * 2 + 1], fv.y, s));
                }
                s += __shfl_xor_sync(0xFFFFFFFFu, s, 1);
                s += __shfl_xor_sync(0xFFFFFFFFu, s, 2);
                if (kq == 0) atomicAdd(&Ofb[grow * 2 + z], s);
            } else {
                #pragma unroll
                for (int ni = 0; ni < NI; ni++) {
                    const int gc = colBlock + wn * WTN + ni * 8 + kq * 2;
                    float v0 = acc[mi][ni][half * 2 + 0] + bias[gc];
                    float v1 = acc[mi][ni][half * 2 + 1] + bias[gc + 1];
                    if (MODE == 0) { v0 = fmaxf(v0, 0.0f); v1 = fmaxf(v1, 0.0f); }
                    const size_t base = (size_t)grow * NOUT + gc;
                    if (MODE == 0 || z == 0) {
                        __half h0 = __float2half(v0);
                        __half h1 = __float2half(v1);
                        __half l0 = __float2half(v0 - __half2float(h0));
                        __half l1 = __float2half(v1 - __half2float(h1));
                        __half* oh = Ohi;
                        __half* ol = Olo;
                        if (MODE == 0) { oh += (size_t)z * OZ; ol += (size_t)z * OZ; }
                        *reinterpret_cast<__half2*>(oh + base) = __halves2half2(h0, h1);
                        *reinterpret_cast<__half2*>(ol + base) = __halves2half2(l0, l1);
                    } else {
                        *reinterpret_cast<float2*>(Ofa + base) = make_float2(v0, v1);
                    }
                }
            }
        }
    }
}

// ---------------------------------------------------------------------------
// Unified prep kernel: x0/x1 split-conv, W_feat / W_br transpose->fp16,
// W_out repack->fp16, out bias-init.  Block-range dispatch, 256 threads.
// ---------------------------------------------------------------------------
#define XB 2048                      // blocks per x conv (524288 float4 / 256)
#define WF_TILES 512                 // (512/32)*(1024/32)
#define WB_TILES 256                 // 2*(256/32)*(512/32)
#define WO_BLKS 64                   // 65536 float2 / 1024
#define OI_BLKS 4                    // 4096 floats / 1024

__device__ __forceinline__ void transpose_tile(
    const float* __restrict__ W, __half* __restrict__ hi,
    int Krows, int Ncols, int bxn, int byk, float (*tile)[33], int tid)
{
    int tx = tid & 31, ty = tid >> 5;     // 32 x 8
    int n0 = bxn * 32, k0 = byk * 32;
    #pragma unroll
    for (int i = 0; i < 32; i += 8)
        tile[ty + i][tx] = W[(size_t)(k0 + ty + i) * Ncols + n0 + tx];
    __syncthreads();
    #pragma unroll
    for (int i = 0; i < 32; i += 8)
        hi[(size_t)(n0 + ty + i) * Krows + k0 + tx] = __float2half(tile[tx][ty + i]);
}

__global__ void __launch_bounds__(256)
prep_kernel(const float* __restrict__ x0, const float* __restrict__ x1,
            const float* __restrict__ W_feat,
            const float* __restrict__ W_br0, const float* __restrict__ W_br1,
            const float* __restrict__ W_out, const float* __restrict__ b_out,
            __half* __restrict__ Xhi, __half* __restrict__ Xlo,
            __half* __restrict__ Wfhi, __half* __restrict__ Wbhi,
            __half* __restrict__ Wohi, float* __restrict__ out)
{
    __shared__ float tile[32][33];
    const int tid = threadIdx.x;
    int bx = blockIdx.x;

    if (bx < 2 * XB) {
        const float* src = (bx < XB) ? x0 : x1;
        size_t zoff = (bx < XB) ? 0 : (size_t)BATCH * IN_DIM;
        int i = (bx & (XB - 1)) * 256 + tid;           // float4 index
        float4 v = reinterpret_cast<const float4*>(src)[i];
        float a[4] = {v.x, v.y, v.z, v.w};
        __half h[4], l[4];
        #pragma unroll
        for (int k = 0; k < 4; k++) {
            h[k] = __float2half(a[k]);
            l[k] = __float2half(a[k] - __half2float(h[k]));
        }
        __half2* hp = reinterpret_cast<__half2*>(Xhi + zoff) + (size_t)i * 2;
        __half2* lp = reinterpret_cast<__half2*>(Xlo + zoff) + (size_t)i * 2;
        hp[0] = __halves2half2(h[0], h[1]);
        hp[1] = __halves2half2(h[2], h[3]);
        lp[0] = __halves2half2(l[0], l[1]);
        lp[1] = __halves2half2(l[2], l[3]);
    } else if (bx < 2 * XB + WF_TILES) {
        int t = bx - 2 * XB;                            // 16 x 32 tiles
        transpose_tile(W_feat, Wfhi, IN_DIM, HID, t & 15, t >> 4, tile, tid);
    } else if (bx < 2 * XB + WF_TILES + WB_TILES) {
        int t = bx - (2 * XB + WF_TILES);               // 2 x (8 x 16)
        int zz = t >> 7; t &= 127;
        transpose_tile(zz ? W_br1 : W_br0, Wbhi + (size_t)zz * FEAT * HID,
                       HID, FEAT, t & 7, t >> 3, tile, tid);
    } else if (bx < 2 * XB + WF_TILES + WB_TILES + WO_BLKS) {
        int t = bx - (2 * XB + WF_TILES + WB_TILES);
        int r = t * 1024 + tid * 4;                     // over FEAT*FEAT
        #pragma unroll
        for (int q = 0; q < 4; q++) {
            float2 w = reinterpret_cast<const float2*>(W_out)[r + q];
            Wohi[r + q]                = __float2half(w.x);
            Wohi[FEAT * FEAT + r + q]  = __float2half(w.y);
        }
    } else {
        int t = bx - (2 * XB + WF_TILES + WB_TILES + WO_BLKS);
        int i = t * 1024 + tid * 4;                     // over 2*BATCH
        float b0 = b_out[0], b1 = b_out[1];
        #pragma unroll
        for (int q = 0; q < 4; q++) out[i + q] = ((i + q) & 1) ? b1 : b0;
    }
}

// ---------------------------- launch ----------------------------------------
extern "C" void kernel_launch(void* const* d_in, const int* in_sizes, int n_in,
                              void* d_out, int out_size)
{
    const float* x0     = (const float*)d_in[0];
    const float* x1     = (const float*)d_in[1];
    const float* W_feat = (const float*)d_in[2];
    const float* b_feat = (const float*)d_in[3];
    const float* W_br0  = (const float*)d_in[4];
    const float* b_br0  = (const float*)d_in[5];
    const float* W_br1  = (const float*)d_in[6];
    const float* b_br1  = (const float*)d_in[7];
    const float* W_out  = (const float*)d_in[8];
    const float* b_out  = (const float*)d_in[9];
    float*       out    = (float*)d_out;

    __half *Xhi, *Xlo, *Wfhi, *Wbhi, *Wohi, *Hhi, *Hlo, *F0hi, *F0lo;
    float *F1;
    cudaGetSymbolAddress((void**)&Xhi, g_Xhi);   cudaGetSymbolAddress((void**)&Xlo, g_Xlo);
    cudaGetSymbolAddress((void**)&Wfhi, g_Wfhi);
    cudaGetSymbolAddress((void**)&Wbhi, g_Wbhi);
    cudaGetSymbolAddress((void**)&Wohi, g_Wohi);
    cudaGetSymbolAddress((void**)&Hhi, g_Hhi);   cudaGetSymbolAddress((void**)&Hlo, g_Hlo);
    cudaGetSymbolAddress((void**)&F0hi, g_F0hi); cudaGetSymbolAddress((void**)&F0lo, g_F0lo);
    cudaGetSymbolAddress((void**)&F1, g_F1);

    // K1: BM=128 BN=128 T=256 KK=1024 -> stage (2*128+128)*80 = 30720, x2 = 61440
    // K2/K3: BM=64 BN=64 T=128 -> stage (2*64+64)*80 = 15360, x2 = 30720
    constexpr int SM1 = 2 * (2 * 128 + 128) * 80;
    constexpr int SM2 = 2 * (2 * 64 + 64) * 80;
    cudaFuncSetAttribute((const void*)gemm_mma<128, 128, 256, 1024, 512, 0>,
                         cudaFuncAttributeMaxDynamicSharedMemorySize, SM1);
    cudaFuncSetAttribute((const void*)gemm_mma<64, 64, 128, 512, 256, 1>,
                         cudaFuncAttributeMaxDynamicSharedMemorySize, SM2);
    cudaFuncSetAttribute((const void*)gemm_mma<64, 64, 128, 256, 256, 2>,
                         cudaFuncAttributeMaxDynamicSharedMemorySize, SM2);

    // one prep launch: conversions + transposes + out init
    prep_kernel<<<2 * XB + WF_TILES + WB_TILES + WO_BLKS + OI_BLKS, 256>>>(
        x0, x1, W_feat, W_br0, W_br1, W_out, b_out,
        Xhi, Xlo, Wfhi, Wbhi, Wohi, out);

    // K1: H_z = relu(x_z @ W_feat + b_feat) -> split fp16 (fused)
    gemm_mma<128, 128, 256, 1024, 512, 0>
        <<<dim3(HID / 128, BATCH / 128, 2), 256, SM1>>>(
        Xhi, Xlo, Wfhi, b_feat, b_feat, Hhi, Hlo, nullptr, nullptr);

    // K2: F_z = H_z @ W_br_z + b_br_z  (z=0 -> split F0, z=1 -> fp32 F1)
    gemm_mma<64, 64, 128, 512, 256, 1>
        <<<dim3(FEAT / 64, BATCH / 64, 2), 128, SM2>>>(
        Hhi, Hlo, Wbhi, b_br0, b_br1, F0hi, F0lo, F1, nullptr);

    // K3 (+fused K4): out[b,z] = b_out[z] + sum_j F1[b,j] * (F0 @ Wo_z^T)[b,j]
    gemm_mma<64, 64, 128, 256, 256, 2>
        <<<dim3(FEAT / 64, BATCH / 64, 2), 128, SM2>>>(
        F0hi, F0lo, Wohi, nullptr, nullptr, nullptr, nullptr, F1, out);
}

// round 6
// speedup vs baseline: 3.9710x; 1.0370x over previous
#include <cuda_runtime.h>
#include <cuda_fp16.h>
#include <cstdint>

#define BATCH   2048
#define IN_DIM  1024
#define HID     512
#define FEAT    256

// ---------------------------------------------------------------------------
// helpers
// ---------------------------------------------------------------------------
__device__ __forceinline__ uint32_t smem_u32(const void* p) {
    uint32_t a;
    asm("{ .reg .u64 t; cvta.to.shared.u64 t, %1; cvt.u32.u64 %0, t; }"
        : "=r"(a) : "l"(p));
    return a;
}

__device__ __forceinline__ void mma16816(float* c, const uint32_t* a, const uint32_t* b)
{
    asm volatile(
        "mma.sync.aligned.m16n8k16.row.col.f32.f16.f16.f32 "
        "{%0,%1,%2,%3}, {%4,%5,%6,%7}, {%8,%9}, {%0,%1,%2,%3};\n"
        : "+f"(c[0]), "+f"(c[1]), "+f"(c[2]), "+f"(c[3])
        : "r"(a[0]), "r"(a[1]), "r"(a[2]), "r"(a[3]), "r"(b[0]), "r"(b[1]));
}

#define LDSM4(r0, r1, r2, r3, addr)                                            \
    asm volatile("ldmatrix.sync.aligned.m8n8.x4.shared.b16 {%0,%1,%2,%3}, [%4];" \
        : "=r"(r0), "=r"(r1), "=r"(r2), "=r"(r3) : "r"(addr))

#define CP16(dst, src)                                                         \
    asm volatile("cp.async.cg.shared.global [%0], [%1], 16;"                   \
        :: "r"(dst), "l"(src))
#define CP_COMMIT() asm volatile("cp.async.commit_group;" ::: "memory")
#define CP_WAIT1()  asm volatile("cp.async.wait_group 1;" ::: "memory")
#define CP_WAIT0()  asm volatile("cp.async.wait_group 0;" ::: "memory")

// ---------------------------- scratch ---------------------------------------
__device__ __align__(16) __half g_Xhi[2 * BATCH * IN_DIM];
__device__ __align__(16) __half g_Xlo[2 * BATCH * IN_DIM];
__device__ __align__(16) __half g_Wfhi[HID * IN_DIM];       // [N=512][K=1024]
__device__ __align__(16) __half g_Wbhi[2 * FEAT * HID];     // [z][N=256][K=512]
__device__ __align__(16) __half g_Wohi[2 * FEAT * FEAT];    // [o][j][i]
__device__ __align__(16) __half g_Hhi[2 * BATCH * HID];
__device__ __align__(16) __half g_Hlo[2 * BATCH * HID];
__device__ __align__(16) __half g_F0hi[BATCH * FEAT];
__device__ __align__(16) __half g_F0lo[BATCH * FEAT];
__device__ __align__(16) float  g_F1[BATCH * FEAT];

// ---------------------------------------------------------------------------
// 2-term split-fp16 mma.sync GEMM, 3-stage cp.async ring pipeline.
//   A[M,KK] row-major fp16 hi/lo; B[NOUT,KK] row-major fp16 (weights).
//   acc fp32 = Ahi*Bhi + Alo*Bhi.
// MODE 0: K1 (bias+relu, split-fp16 out)
// MODE 1: K2 (bias; z=0 -> split F0, z=1 -> fp32 F1)
// MODE 2: K3 (fused final dot into out via atomics)
// ---------------------------------------------------------------------------
template <int BM, int BN, int THREADS, int KK, int NOUT, int MODE, int MINB>
__global__ void __launch_bounds__(THREADS, MINB)
gemm_mma(const __half* __restrict__ Ahi, const __half* __restrict__ Alo,
         const __half* __restrict__ Bhi,
         const float* __restrict__ bias0, const float* __restrict__ bias1,
         __half* __restrict__ Ohi, __half* __restrict__ Olo,
         float* __restrict__ Ofa, float* __restrict__ Ofb)
{
    constexpr int BK   = 32;                  // halves per stage
    constexpr int ROWB = 80;                  // 64B data + 16B pad
    constexpr int T    = KK / BK;
    constexpr int WARPS = THREADS / 32;
    constexpr int WN_W = (BN == 128) ? 4 : 2;
    constexpr int WM_W = WARPS / WN_W;
    constexpr int WTM  = BM / WM_W;
    constexpr int WTN  = BN / WN_W;
    constexpr int MI   = WTM / 16;
    constexpr int NI   = WTN / 8;
    constexpr int STAGE = (2 * BM + BN) * ROWB;
    constexpr size_t AZ = (MODE == 0) ? (size_t)BATCH * IN_DIM
                         : (MODE == 1) ? (size_t)BATCH * HID : 0;
    constexpr size_t BZ = (MODE == 0) ? 0
                         : (MODE == 1) ? (size_t)FEAT * HID : (size_t)FEAT * FEAT;
    constexpr size_t OZ = (size_t)BATCH * NOUT;

    extern __shared__ char dsm[];
    const uint32_t sbase = smem_u32(dsm);

    const int tid  = threadIdx.x;
    const int lane = tid & 31;
    const int warp = tid >> 5;
    const int wm = warp / WN_W, wn = warp % WN_W;
    const int z = blockIdx.z;
    const int rowBlock = blockIdx.y * BM;
    const int colBlock = blockIdx.x * BN;

    Ahi += (size_t)z * AZ;  Alo += (size_t)z * AZ;
    Bhi += (size_t)z * BZ;
    const float* bias = z ? bias1 : bias0;

    auto stage = [&](int t, int buf_i) {
        const int kt = t * BK;
        const uint32_t buf = sbase + buf_i * STAGE;
        #pragma unroll
        for (int i = 0; i < BM * 4 / THREADS; i++) {
            int slot = tid + i * THREADS;
            int row = slot >> 2, ch = slot & 3;
            uint32_t d = buf + row * ROWB + ch * 16;
            CP16(d, Ahi + (size_t)(rowBlock + row) * KK + kt + ch * 8);
            CP16(d + BM * ROWB, Alo + (size_t)(rowBlock + row) * KK + kt + ch * 8);
        }
        #pragma unroll
        for (int i = 0; i < BN * 4 / THREADS; i++) {
            int slot = tid + i * THREADS;
            int row = slot >> 2, ch = slot & 3;
            CP16(buf + (2 * BM + row) * ROWB + ch * 16,
                 Bhi + (size_t)(colBlock + row) * KK + kt + ch * 8);
        }
        CP_COMMIT();
    };

    float acc[MI][NI][4];
    #pragma unroll
    for (int mi = 0; mi < MI; mi++)
        #pragma unroll
        for (int ni = 0; ni < NI; ni++)
            #pragma unroll
            for (int r = 0; r < 4; r++) acc[mi][ni][r] = 0.0f;

    const uint32_t aOff = (uint32_t)((wm * WTM + (lane & 15)) * ROWB + (lane >> 4) * 16);
    const uint32_t bOff = (uint32_t)((wn * WTN + ((lane >> 4) << 3) + (lane & 7)) * ROWB
                                     + ((lane >> 3) & 1) * 16);

    // 3-stage ring: prologue loads stages 0,1
    stage(0, 0);
    stage(1, 1);
    int bc = 0;           // buffer index of stage t
    int bn2 = 2;          // buffer index for stage t+2

    #pragma unroll 1
    for (int t = 0; t < T; t++) {
        CP_WAIT1();                 // stage t complete (t+1 may be pending)
        __syncthreads();            // all warps past iter t-1 reads of buf bn2
        if (t + 2 < T) stage(t + 2, bn2);

        const uint32_t buf  = sbase + bc * STAGE;
        const uint32_t aHiB = buf + aOff;
        const uint32_t aLoB = aHiB + BM * ROWB;
        const uint32_t bHiB = buf + 2 * BM * ROWB + bOff;

        #pragma unroll
        for (int ks = 0; ks < 2; ks++) {
            const uint32_t ko = ks * 32;   // 16 halves = 32B
            uint32_t ah[MI][4], al[MI][4];
            #pragma unroll
            for (int mi = 0; mi < MI; mi++) {
                LDSM4(ah[mi][0], ah[mi][1], ah[mi][2], ah[mi][3],
                      aHiB + mi * 16 * ROWB + ko);
                LDSM4(al[mi][0], al[mi][1], al[mi][2], al[mi][3],
                      aLoB + mi * 16 * ROWB + ko);
            }
            uint32_t bh[NI][2];
            #pragma unroll
            for (int np = 0; np < NI / 2; np++) {
                LDSM4(bh[np * 2][0], bh[np * 2][1], bh[np * 2 + 1][0], bh[np * 2 + 1][1],
                      bHiB + np * 16 * ROWB + ko);
            }
            #pragma unroll
            for (int mi = 0; mi < MI; mi++)
                #pragma unroll
                for (int ni = 0; ni < NI; ni++) {
                    mma16816(acc[mi][ni], ah[mi], bh[ni]);
                    mma16816(acc[mi][ni], al[mi], bh[ni]);
                }
        }
        bc = (bc == 2) ? 0 : bc + 1;
        bn2 = (bn2 == 2) ? 0 : bn2 + 1;
    }

    // ------------------------------ epilogue --------------------------------
    const int g  = lane >> 2;
    const int kq = lane & 3;
    #pragma unroll
    for (int mi = 0; mi < MI; mi++) {
        #pragma unroll
        for (int half = 0; half < 2; half++) {
            const int grow = rowBlock + wm * WTM + mi * 16 + half * 8 + g;
            if (MODE == 2) {
                const float* F1p = Ofa;
                float s = 0.0f;
                #pragma unroll
                for (int ni = 0; ni < NI; ni++) {
                    const int gc = colBlock + wn * WTN + ni * 8 + kq * 2;
                    float2 fv = *reinterpret_cast<const float2*>(
                        F1p + (size_t)grow * FEAT + gc);
                    s = fmaf(acc[mi][ni][half * 2 + 0], fv.x,
                        fmaf(acc[mi][ni][half * 2 + 1], fv.y, s));
                }
                s += __shfl_xor_sync(0xFFFFFFFFu, s, 1);
                s += __shfl_xor_sync(0xFFFFFFFFu, s, 2);
                if (kq == 0) atomicAdd(&Ofb[grow * 2 + z], s);
            } else {
                #pragma unroll
                for (int ni = 0; ni < NI; ni++) {
                    const int gc = colBlock + wn * WTN + ni * 8 + kq * 2;
                    float v0 = acc[mi][ni][half * 2 + 0] + bias[gc];
                    float v1 = acc[mi][ni][half * 2 + 1] + bias[gc + 1];
                    if (MODE == 0) { v0 = fmaxf(v0, 0.0f); v1 = fmaxf(v1, 0.0f); }
                    const size_t base = (size_t)grow * NOUT + gc;
                    if (MODE == 0 || z == 0) {
                        __half h0 = __float2half(v0);
                        __half h1 = __float2half(v1);
                        __half l0 = __float2half(v0 - __half2float(h0));
                        __half l1 = __float2half(v1 - __half2float(h1));
                        __half* oh = Ohi;
                        __half* ol = Olo;
                        if (MODE == 0) { oh += (size_t)z * OZ; ol += (size_t)z * OZ; }
                        *reinterpret_cast<__half2*>(oh + base) = __halves2half2(h0, h1);
                        *reinterpret_cast<__half2*>(ol + base) = __halves2half2(l0, l1);
                    } else {
                        *reinterpret_cast<float2*>(Ofa + base) = make_float2(v0, v1);
                    }
                }
            }
        }
    }
}

// ---------------------------------------------------------------------------
// Unified prep kernel (unchanged from R5)
// ---------------------------------------------------------------------------
#define XB 2048
#define WF_TILES 512
#define WB_TILES 256
#define WO_BLKS 64
#define OI_BLKS 4

__device__ __forceinline__ void transpose_tile(
    const float* __restrict__ W, __half* __restrict__ hi,
    int Krows, int Ncols, int bxn, int byk, float (*tile)[33], int tid)
{
    int tx = tid & 31, ty = tid >> 5;
    int n0 = bxn * 32, k0 = byk * 32;
    #pragma unroll
    for (int i = 0; i < 32; i += 8)
        tile[ty + i][tx] = W[(size_t)(k0 + ty + i) * Ncols + n0 + tx];
    __syncthreads();
    #pragma unroll
    for (int i = 0; i < 32; i += 8)
        hi[(size_t)(n0 + ty + i) * Krows + k0 + tx] = __float2half(tile[tx][ty + i]);
}

__global__ void __launch_bounds__(256)
prep_kernel(const float* __restrict__ x0, const float* __restrict__ x1,
            const float* __restrict__ W_feat,
            const float* __restrict__ W_br0, const float* __restrict__ W_br1,
            const float* __restrict__ W_out, const float* __restrict__ b_out,
            __half* __restrict__ Xhi, __half* __restrict__ Xlo,
            __half* __restrict__ Wfhi, __half* __restrict__ Wbhi,
            __half* __restrict__ Wohi, float* __restrict__ out)
{
    __shared__ float tile[32][33];
    const int tid = threadIdx.x;
    int bx = blockIdx.x;

    if (bx < 2 * XB) {
        const float* src = (bx < XB) ? x0 : x1;
        size_t zoff = (bx < XB) ? 0 : (size_t)BATCH * IN_DIM;
        int i = (bx & (XB - 1)) * 256 + tid;
        float4 v = reinterpret_cast<const float4*>(src)[i];
        float a[4] = {v.x, v.y, v.z, v.w};
        __half h[4], l[4];
        #pragma unroll
        for (int k = 0; k < 4; k++) {
            h[k] = __float2half(a[k]);
            l[k] = __float2half(a[k] - __half2float(h[k]));
        }
        __half2* hp = reinterpret_cast<__half2*>(Xhi + zoff) + (size_t)i * 2;
        __half2* lp = reinterpret_cast<__half2*>(Xlo + zoff) + (size_t)i * 2;
        hp[0] = __halves2half2(h[0], h[1]);
        hp[1] = __halves2half2(h[2], h[3]);
        lp[0] = __halves2half2(l[0], l[1]);
        lp[1] = __halves2half2(l[2], l[3]);
    } else if (bx < 2 * XB + WF_TILES) {
        int t = bx - 2 * XB;
        transpose_tile(W_feat, Wfhi, IN_DIM, HID, t & 15, t >> 4, tile, tid);
    } else if (bx < 2 * XB + WF_TILES + WB_TILES) {
        int t = bx - (2 * XB + WF_TILES);
        int zz = t >> 7; t &= 127;
        transpose_tile(zz ? W_br1 : W_br0, Wbhi + (size_t)zz * FEAT * HID,
                       HID, FEAT, t & 7, t >> 3, tile, tid);
    } else if (bx < 2 * XB + WF_TILES + WB_TILES + WO_BLKS) {
        int t = bx - (2 * XB + WF_TILES + WB_TILES);
        int r = t * 1024 + tid * 4;
        #pragma unroll
        for (int q = 0; q < 4; q++) {
            float2 w = reinterpret_cast<const float2*>(W_out)[r + q];
            Wohi[r + q]                = __float2half(w.x);
            Wohi[FEAT * FEAT + r + q]  = __float2half(w.y);
        }
    } else {
        int t = bx - (2 * XB + WF_TILES + WB_TILES + WO_BLKS);
        int i = t * 1024 + tid * 4;
        float b0 = b_out[0], b1 = b_out[1];
        #pragma unroll
        for (int q = 0; q < 4; q++) out[i + q] = ((i + q) & 1) ? b1 : b0;
    }
}

// ---------------------------- launch ----------------------------------------
extern "C" void kernel_launch(void* const* d_in, const int* in_sizes, int n_in,
                              void* d_out, int out_size)
{
    const float* x0     = (const float*)d_in[0];
    const float* x1     = (const float*)d_in[1];
    const float* W_feat = (const float*)d_in[2];
    const float* b_feat = (const float*)d_in[3];
    const float* W_br0  = (const float*)d_in[4];
    const float* b_br0  = (const float*)d_in[5];
    const float* W_br1  = (const float*)d_in[6];
    const float* b_br1  = (const float*)d_in[7];
    const float* W_out  = (const float*)d_in[8];
    const float* b_out  = (const float*)d_in[9];
    float*       out    = (float*)d_out;

    __half *Xhi, *Xlo, *Wfhi, *Wbhi, *Wohi, *Hhi, *Hlo, *F0hi, *F0lo;
    float *F1;
    cudaGetSymbolAddress((void**)&Xhi, g_Xhi);   cudaGetSymbolAddress((void**)&Xlo, g_Xlo);
    cudaGetSymbolAddress((void**)&Wfhi, g_Wfhi);
    cudaGetSymbolAddress((void**)&Wbhi, g_Wbhi);
    cudaGetSymbolAddress((void**)&Wohi, g_Wohi);
    cudaGetSymbolAddress((void**)&Hhi, g_Hhi);   cudaGetSymbolAddress((void**)&Hlo, g_Hlo);
    cudaGetSymbolAddress((void**)&F0hi, g_F0hi); cudaGetSymbolAddress((void**)&F0lo, g_F0lo);
    cudaGetSymbolAddress((void**)&F1, g_F1);

    // 3-stage smem: K1 stage (2*128+128)*80 = 30720 -> 92160
    //               K2/K3 stage (2*64+64)*80 = 15360 -> 46080
    constexpr int SM1 = 3 * (2 * 128 + 128) * 80;
    constexpr int SM2 = 3 * (2 * 64 + 64) * 80;
    cudaFuncSetAttribute((const void*)gemm_mma<128, 128, 256, 1024, 512, 0, 2>,
                         cudaFuncAttributeMaxDynamicSharedMemorySize, SM1);
    cudaFuncSetAttribute((const void*)gemm_mma<64, 64, 128, 512, 256, 1, 4>,
                         cudaFuncAttributeMaxDynamicSharedMemorySize, SM2);
    cudaFuncSetAttribute((const void*)gemm_mma<64, 64, 128, 256, 256, 2, 4>,
                         cudaFuncAttributeMaxDynamicSharedMemorySize, SM2);

    prep_kernel<<<2 * XB + WF_TILES + WB_TILES + WO_BLKS + OI_BLKS, 256>>>(
        x0, x1, W_feat, W_br0, W_br1, W_out, b_out,
        Xhi, Xlo, Wfhi, Wbhi, Wohi, out);

    // K1
    gemm_mma<128, 128, 256, 1024, 512, 0, 2>
        <<<dim3(HID / 128, BATCH / 128, 2), 256, SM1>>>(
        Xhi, Xlo, Wfhi, b_feat, b_feat, Hhi, Hlo, nullptr, nullptr);

    // K2
    gemm_mma<64, 64, 128, 512, 256, 1, 4>
        <<<dim3(FEAT / 64, BATCH / 64, 2), 128, SM2>>>(
        Hhi, Hlo, Wbhi, b_br0, b_br1, F0hi, F0lo, F1, nullptr);

    // K3 (+fused K4)
    gemm_mma<64, 64, 128, 256, 256, 2, 4>
        <<<dim3(FEAT / 64, BATCH / 64, 2), 128, SM2>>>(
        F0hi, F0lo, Wohi, nullptr, nullptr, nullptr, nullptr, F1, out);
}

// round 7
// speedup vs baseline: 4.0397x; 1.0173x over previous
#include <cuda_runtime.h>
#include <cuda_fp16.h>
#include <cstdint>

#define BATCH   2048
#define IN_DIM  1024
#define HID     512
#define FEAT    256

// ---------------------------------------------------------------------------
// helpers
// ---------------------------------------------------------------------------
__device__ __forceinline__ uint32_t smem_u32(const void* p) {
    uint32_t a;
    asm("{ .reg .u64 t; cvta.to.shared.u64 t, %1; cvt.u32.u64 %0, t; }"
        : "=r"(a) : "l"(p));
    return a;
}

__device__ __forceinline__ void mma16816(float* c, const uint32_t* a, const uint32_t* b)
{
    asm volatile(
        "mma.sync.aligned.m16n8k16.row.col.f32.f16.f16.f32 "
        "{%0,%1,%2,%3}, {%4,%5,%6,%7}, {%8,%9}, {%0,%1,%2,%3};\n"
        : "+f"(c[0]), "+f"(c[1]), "+f"(c[2]), "+f"(c[3])
        : "r"(a[0]), "r"(a[1]), "r"(a[2]), "r"(a[3]), "r"(b[0]), "r"(b[1]));
}

#define LDSM4(r0, r1, r2, r3, addr)                                            \
    asm volatile("ldmatrix.sync.aligned.m8n8.x4.shared.b16 {%0,%1,%2,%3}, [%4];" \
        : "=r"(r0), "=r"(r1), "=r"(r2), "=r"(r3) : "r"(addr))

#define CP16(dst, src)                                                         \
    asm volatile("cp.async.cg.shared.global [%0], [%1], 16;"                   \
        :: "r"(dst), "l"(src))
#define CP_COMMIT() asm volatile("cp.async.commit_group;" ::: "memory")
#define CP_WAIT1()  asm volatile("cp.async.wait_group 1;" ::: "memory")

// ---------------------------- scratch ---------------------------------------
__device__ __align__(16) __half g_Xhi[2 * BATCH * IN_DIM];
__device__ __align__(16) __half g_Xlo[2 * BATCH * IN_DIM];
__device__ __align__(16) __half g_Wfhi[HID * IN_DIM];       // [N=512][K=1024]
__device__ __align__(16) __half g_Wbhi[2 * FEAT * HID];     // [z][N=256][K=512]
__device__ __align__(16) __half g_Wohi[2 * FEAT * FEAT];    // [o][j][i]
__device__ __align__(16) __half g_Hhi[2 * BATCH * HID];
__device__ __align__(16) __half g_Hlo[2 * BATCH * HID];
__device__ __align__(16) __half g_F0hi[BATCH * FEAT];
__device__ __align__(16) __half g_F0lo[BATCH * FEAT];
__device__ __align__(16) float  g_F1[BATCH * FEAT];

// ---------------------------------------------------------------------------
// 2-term split-fp16 mma.sync GEMM, 3-stage cp.async ring.
//   acc fp32 = Ahi*Bhi + Alo*Bhi
// MODE 0: K1 (bias+relu, split-fp16 out)
// MODE 1: K2 (bias; z=0 -> split F0, z=1 -> fp32 F1)
// MODE 2: K3 (fused final dot into out via atomics)
// ---------------------------------------------------------------------------
template <int BM, int BN, int THREADS, int KK, int NOUT, int MODE, int MINB>
__global__ void __launch_bounds__(THREADS, MINB)
gemm_mma(const __half* __restrict__ Ahi, const __half* __restrict__ Alo,
         const __half* __restrict__ Bhi,
         const float* __restrict__ bias0, const float* __restrict__ bias1,
         __half* __restrict__ Ohi, __half* __restrict__ Olo,
         float* __restrict__ Ofa, float* __restrict__ Ofb)
{
    constexpr int BK   = 32;                  // halves per stage
    constexpr int ROWB = 80;                  // 64B data + 16B pad
    constexpr int T    = KK / BK;
    constexpr int WARPS = THREADS / 32;
    constexpr int WN_W = (BN == 128) ? 4 : 2;
    constexpr int WM_W = WARPS / WN_W;
    constexpr int WTM  = BM / WM_W;
    constexpr int WTN  = BN / WN_W;
    constexpr int MI   = WTM / 16;
    constexpr int NI   = WTN / 8;
    constexpr int STAGE = (2 * BM + BN) * ROWB;
    constexpr size_t AZ = (MODE == 0) ? (size_t)BATCH * IN_DIM
                         : (MODE == 1) ? (size_t)BATCH * HID : 0;
    constexpr size_t BZ = (MODE == 0) ? 0
                         : (MODE == 1) ? (size_t)FEAT * HID : (size_t)FEAT * FEAT;
    constexpr size_t OZ = (size_t)BATCH * NOUT;

    extern __shared__ char dsm[];
    const uint32_t sbase = smem_u32(dsm);

    const int tid  = threadIdx.x;
    const int lane = tid & 31;
    const int warp = tid >> 5;
    const int wm = warp / WN_W, wn = warp % WN_W;
    const int z = blockIdx.z;
    const int rowBlock = blockIdx.y * BM;
    const int colBlock = blockIdx.x * BN;

    Ahi += (size_t)z * AZ;  Alo += (size_t)z * AZ;
    Bhi += (size_t)z * BZ;
    const float* bias = z ? bias1 : bias0;

    auto stage = [&](int t, int buf_i) {
        const int kt = t * BK;
        const uint32_t buf = sbase + buf_i * STAGE;
        #pragma unroll
        for (int i = 0; i < BM * 4 / THREADS; i++) {
            int slot = tid + i * THREADS;
            int row = slot >> 2, ch = slot & 3;
            uint32_t d = buf + row * ROWB + ch * 16;
            CP16(d, Ahi + (size_t)(rowBlock + row) * KK + kt + ch * 8);
            CP16(d + BM * ROWB, Alo + (size_t)(rowBlock + row) * KK + kt + ch * 8);
        }
        #pragma unroll
        for (int i = 0; i < BN * 4 / THREADS; i++) {
            int slot = tid + i * THREADS;
            int row = slot >> 2, ch = slot & 3;
            CP16(buf + (2 * BM + row) * ROWB + ch * 16,
                 Bhi + (size_t)(colBlock + row) * KK + kt + ch * 8);
        }
        CP_COMMIT();
    };

    float acc[MI][NI][4];
    #pragma unroll
    for (int mi = 0; mi < MI; mi++)
        #pragma unroll
        for (int ni = 0; ni < NI; ni++)
            #pragma unroll
            for (int r = 0; r < 4; r++) acc[mi][ni][r] = 0.0f;

    const uint32_t aOff = (uint32_t)((wm * WTM + (lane & 15)) * ROWB + (lane >> 4) * 16);
    const uint32_t bOff = (uint32_t)((wn * WTN + ((lane >> 4) << 3) + (lane & 7)) * ROWB
                                     + ((lane >> 3) & 1) * 16);

    // 3-stage ring
    stage(0, 0);
    stage(1, 1);
    int bc = 0, bn2 = 2;

    #pragma unroll 1
    for (int t = 0; t < T; t++) {
        CP_WAIT1();
        __syncthreads();
        if (t + 2 < T) stage(t + 2, bn2);

        const uint32_t buf  = sbase + bc * STAGE;
        const uint32_t aHiB = buf + aOff;
        const uint32_t aLoB = aHiB + BM * ROWB;
        const uint32_t bHiB = buf + 2 * BM * ROWB + bOff;

        #pragma unroll
        for (int ks = 0; ks < 2; ks++) {
            const uint32_t ko = ks * 32;   // 16 halves = 32B
            uint32_t ah[MI][4], al[MI][4];
            #pragma unroll
            for (int mi = 0; mi < MI; mi++) {
                LDSM4(ah[mi][0], ah[mi][1], ah[mi][2], ah[mi][3],
                      aHiB + mi * 16 * ROWB + ko);
                LDSM4(al[mi][0], al[mi][1], al[mi][2], al[mi][3],
                      aLoB + mi * 16 * ROWB + ko);
            }
            uint32_t bh[NI][2];
            #pragma unroll
            for (int np = 0; np < NI / 2; np++) {
                LDSM4(bh[np * 2][0], bh[np * 2][1], bh[np * 2 + 1][0], bh[np * 2 + 1][1],
                      bHiB + np * 16 * ROWB + ko);
            }
            #pragma unroll
            for (int mi = 0; mi < MI; mi++)
                #pragma unroll
                for (int ni = 0; ni < NI; ni++) {
                    mma16816(acc[mi][ni], ah[mi], bh[ni]);
                    mma16816(acc[mi][ni], al[mi], bh[ni]);
                }
        }
        bc = (bc == 2) ? 0 : bc + 1;
        bn2 = (bn2 == 2) ? 0 : bn2 + 1;
    }

    // ------------------------------ epilogue --------------------------------
    const int g  = lane >> 2;
    const int kq = lane & 3;
    #pragma unroll
    for (int mi = 0; mi < MI; mi++) {
        #pragma unroll
        for (int half = 0; half < 2; half++) {
            const int grow = rowBlock + wm * WTM + mi * 16 + half * 8 + g;
            if (MODE == 2) {
                const float* F1p = Ofa;
                float s = 0.0f;
                #pragma unroll
                for (int ni = 0; ni < NI; ni++) {
                    const int gc = colBlock + wn * WTN + ni * 8 + kq * 2;
                    float2 fv = *reinterpret_cast<const float2*>(
                        F1p + (size_t)grow * FEAT + gc);
                    s = fmaf(acc[mi][ni][half * 2 + 0], fv.x,
                        fmaf(acc[mi][ni][half * 2 + 1], fv.y, s));
                }
                s += __shfl_xor_sync(0xFFFFFFFFu, s, 1);
                s += __shfl_xor_sync(0xFFFFFFFFu, s, 2);
                if (kq == 0) atomicAdd(&Ofb[grow * 2 + z], s);
            } else {
                #pragma unroll
                for (int ni = 0; ni < NI; ni++) {
                    const int gc = colBlock + wn * WTN + ni * 8 + kq * 2;
                    float v0 = acc[mi][ni][half * 2 + 0] + bias[gc];
                    float v1 = acc[mi][ni][half * 2 + 1] + bias[gc + 1];
                    if (MODE == 0) { v0 = fmaxf(v0, 0.0f); v1 = fmaxf(v1, 0.0f); }
                    const size_t base = (size_t)grow * NOUT + gc;
                    if (MODE == 0 || z == 0) {
                        __half h0 = __float2half(v0);
                        __half h1 = __float2half(v1);
                        __half l0 = __float2half(v0 - __half2float(h0));
                        __half l1 = __float2half(v1 - __half2float(h1));
                        __half* oh = Ohi;
                        __half* ol = Olo;
                        if (MODE == 0) { oh += (size_t)z * OZ; ol += (size_t)z * OZ; }
                        *reinterpret_cast<__half2*>(oh + base) = __halves2half2(h0, h1);
                        *reinterpret_cast<__half2*>(ol + base) = __halves2half2(l0, l1);
                    } else {
                        *reinterpret_cast<float2*>(Ofa + base) = make_float2(v0, v1);
                    }
                }
            }
        }
    }
}

// ---------------------------------------------------------------------------
// Unified prep kernel
// ---------------------------------------------------------------------------
#define XB 2048
#define WF_TILES 512
#define WB_TILES 256
#define WO_BLKS 64
#define OI_BLKS 4

__device__ __forceinline__ void transpose_tile(
    const float* __restrict__ W, __half* __restrict__ hi,
    int Krows, int Ncols, int bxn, int byk, float (*tile)[33], int tid)
{
    int tx = tid & 31, ty = tid >> 5;
    int n0 = bxn * 32, k0 = byk * 32;
    #pragma unroll
    for (int i = 0; i < 32; i += 8)
        tile[ty + i][tx] = W[(size_t)(k0 + ty + i) * Ncols + n0 + tx];
    __syncthreads();
    #pragma unroll
    for (int i = 0; i < 32; i += 8)
        hi[(size_t)(n0 + ty + i) * Krows + k0 + tx] = __float2half(tile[tx][ty + i]);
}

__global__ void __launch_bounds__(256)
prep_kernel(const float* __restrict__ x0, const float* __restrict__ x1,
            const float* __restrict__ W_feat,
            const float* __restrict__ W_br0, const float* __restrict__ W_br1,
            const float* __restrict__ W_out, const float* __restrict__ b_out,
            __half* __restrict__ Xhi, __half* __restrict__ Xlo,
            __half* __restrict__ Wfhi, __half* __restrict__ Wbhi,
            __half* __restrict__ Wohi, float* __restrict__ out)
{
    __shared__ float tile[32][33];
    const int tid = threadIdx.x;
    int bx = blockIdx.x;

    if (bx < 2 * XB) {
        const float* src = (bx < XB) ? x0 : x1;
        size_t zoff = (bx < XB) ? 0 : (size_t)BATCH * IN_DIM;
        int i = (bx & (XB - 1)) * 256 + tid;
        float4 v = reinterpret_cast<const float4*>(src)[i];
        float a[4] = {v.x, v.y, v.z, v.w};
        __half h[4], l[4];
        #pragma unroll
        for (int k = 0; k < 4; k++) {
            h[k] = __float2half(a[k]);
            l[k] = __float2half(a[k] - __half2float(h[k]));
        }
        __half2* hp = reinterpret_cast<__half2*>(Xhi + zoff) + (size_t)i * 2;
        __half2* lp = reinterpret_cast<__half2*>(Xlo + zoff) + (size_t)i * 2;
        hp[0] = __halves2half2(h[0], h[1]);
        hp[1] = __halves2half2(h[2], h[3]);
        lp[0] = __halves2half2(l[0], l[1]);
        lp[1] = __halves2half2(l[2], l[3]);
    } else if (bx < 2 * XB + WF_TILES) {
        int t = bx - 2 * XB;
        transpose_tile(W_feat, Wfhi, IN_DIM, HID, t & 15, t >> 4, tile, tid);
    } else if (bx < 2 * XB + WF_TILES + WB_TILES) {
        int t = bx - (2 * XB + WF_TILES);
        int zz = t >> 7; t &= 127;
        transpose_tile(zz ? W_br1 : W_br0, Wbhi + (size_t)zz * FEAT * HID,
                       HID, FEAT, t & 7, t >> 3, tile, tid);
    } else if (bx < 2 * XB + WF_TILES + WB_TILES + WO_BLKS) {
        int t = bx - (2 * XB + WF_TILES + WB_TILES);
        int r = t * 1024 + tid * 4;
        #pragma unroll
        for (int q = 0; q < 4; q++) {
            float2 w = reinterpret_cast<const float2*>(W_out)[r + q];
            Wohi[r + q]                = __float2half(w.x);
            Wohi[FEAT * FEAT + r + q]  = __float2half(w.y);
        }
    } else {
        int t = bx - (2 * XB + WF_TILES + WB_TILES + WO_BLKS);
        int i = t * 1024 + tid * 4;
        float b0 = b_out[0], b1 = b_out[1];
        #pragma unroll
        for (int q = 0; q < 4; q++) out[i + q] = ((i + q) & 1) ? b1 : b0;
    }
}

// ---------------------------- launch ----------------------------------------
extern "C" void kernel_launch(void* const* d_in, const int* in_sizes, int n_in,
                              void* d_out, int out_size)
{
    const float* x0     = (const float*)d_in[0];
    const float* x1     = (const float*)d_in[1];
    const float* W_feat = (const float*)d_in[2];
    const float* b_feat = (const float*)d_in[3];
    const float* W_br0  = (const float*)d_in[4];
    const float* b_br0  = (const float*)d_in[5];
    const float* W_br1  = (const float*)d_in[6];
    const float* b_br1  = (const float*)d_in[7];
    const float* W_out  = (const float*)d_in[8];
    const float* b_out  = (const float*)d_in[9];
    float*       out    = (float*)d_out;

    __half *Xhi, *Xlo, *Wfhi, *Wbhi, *Wohi, *Hhi, *Hlo, *F0hi, *F0lo;
    float *F1;
    cudaGetSymbolAddress((void**)&Xhi, g_Xhi);   cudaGetSymbolAddress((void**)&Xlo, g_Xlo);
    cudaGetSymbolAddress((void**)&Wfhi, g_Wfhi);
    cudaGetSymbolAddress((void**)&Wbhi, g_Wbhi);
    cudaGetSymbolAddress((void**)&Wohi, g_Wohi);
    cudaGetSymbolAddress((void**)&Hhi, g_Hhi);   cudaGetSymbolAddress((void**)&Hlo, g_Hlo);
    cudaGetSymbolAddress((void**)&F0hi, g_F0hi); cudaGetSymbolAddress((void**)&F0lo, g_F0lo);
    cudaGetSymbolAddress((void**)&F1, g_F1);

    // K1:  BM=64  BN=128 T=256 -> stage (128+128)*80 = 20480, x3 = 61440
    // K2/3: BM=32 BN=64  T=128 -> stage (64+64)*80  = 10240, x3 = 30720
    constexpr int SM1 = 3 * (2 * 64 + 128) * 80;
    constexpr int SM2 = 3 * (2 * 32 + 64) * 80;
    cudaFuncSetAttribute((const void*)gemm_mma<64, 128, 256, 1024, 512, 0, 2>,
                         cudaFuncAttributeMaxDynamicSharedMemorySize, SM1);
    cudaFuncSetAttribute((const void*)gemm_mma<32, 64, 128, 512, 256, 1, 4>,
                         cudaFuncAttributeMaxDynamicSharedMemorySize, SM2);
    cudaFuncSetAttribute((const void*)gemm_mma<32, 64, 128, 256, 256, 2, 4>,
                         cudaFuncAttributeMaxDynamicSharedMemorySize, SM2);

    prep_kernel<<<2 * XB + WF_TILES + WB_TILES + WO_BLKS + OI_BLKS, 256>>>(
        x0, x1, W_feat, W_br0, W_br1, W_out, b_out,
        Xhi, Xlo, Wfhi, Wbhi, Wohi, out);

    // K1: grid (512/128, 2048/64, 2) = (4, 32, 2) = 256 CTAs x 8 warps
    gemm_mma<64, 128, 256, 1024, 512, 0, 2>
        <<<dim3(HID / 128, BATCH / 64, 2), 256, SM1>>>(
        Xhi, Xlo, Wfhi, b_feat, b_feat, Hhi, Hlo, nullptr, nullptr);

    // K2: grid (256/64, 2048/32, 2) = (4, 64, 2) = 512 CTAs x 4 warps
    gemm_mma<32, 64, 128, 512, 256, 1, 4>
        <<<dim3(FEAT / 64, BATCH / 32, 2), 128, SM2>>>(
        Hhi, Hlo, Wbhi, b_br0, b_br1, F0hi, F0lo, F1, nullptr);

    // K3 (+fused K4): 512 CTAs x 4 warps
    gemm_mma<32, 64, 128, 256, 256, 2, 4>
        <<<dim3(FEAT / 64, BATCH / 32, 2), 128, SM2>>>(
        F0hi, F0lo, Wohi, nullptr, nullptr, nullptr, nullptr, F1, out);
}

// round 8
// speedup vs baseline: 4.9152x; 1.2167x over previous
#include <cuda_runtime.h>
#include <cuda_fp16.h>
#include <cstdint>

#define BATCH   2048
#define IN_DIM  1024
#define HID     512
#define FEAT    256

// ---------------------------------------------------------------------------
// helpers
// ---------------------------------------------------------------------------
__device__ __forceinline__ uint32_t smem_u32(const void* p) {
    uint32_t a;
    asm("{ .reg .u64 t; cvta.to.shared.u64 t, %1; cvt.u32.u64 %0, t; }"
        : "=r"(a) : "l"(p));
    return a;
}

__device__ __forceinline__ void mma16816(float* c, const uint32_t* a, const uint32_t* b)
{
    asm volatile(
        "mma.sync.aligned.m16n8k16.row.col.f32.f16.f16.f32 "
        "{%0,%1,%2,%3}, {%4,%5,%6,%7}, {%8,%9}, {%0,%1,%2,%3};\n"
        : "+f"(c[0]), "+f"(c[1]), "+f"(c[2]), "+f"(c[3])
        : "r"(a[0]), "r"(a[1]), "r"(a[2]), "r"(a[3]), "r"(b[0]), "r"(b[1]));
}

#define LDSM4(r0, r1, r2, r3, addr)                                            \
    asm volatile("ldmatrix.sync.aligned.m8n8.x4.shared.b16 {%0,%1,%2,%3}, [%4];" \
        : "=r"(r0), "=r"(r1), "=r"(r2), "=r"(r3) : "r"(addr))

#define CP16(dst, src)                                                         \
    asm volatile("cp.async.cg.shared.global [%0], [%1], 16;"                   \
        :: "r"(dst), "l"(src))
#define CP_COMMIT() asm volatile("cp.async.commit_group;" ::: "memory")
#define CP_WAIT1()  asm volatile("cp.async.wait_group 1;" ::: "memory")

// ---------------------------- scratch ---------------------------------------
__device__ __align__(16) __half g_Xhi[2 * BATCH * IN_DIM];     // plain fp16 x
__device__ __align__(16) __half g_Wfhi[HID * IN_DIM];          // [N=512][K=1024]
__device__ __align__(16) __half g_Wbhi[2 * FEAT * HID];        // [z][N=256][K=512]
__device__ __align__(16) __half g_Wohi[2 * FEAT * FEAT];       // [o][j][i]
__device__ __align__(16) __half g_Hhi[2 * BATCH * HID];
__device__ __align__(16) __half g_Hlo[2 * BATCH * HID];
__device__ __align__(16) __half g_F0hi[BATCH * FEAT];
__device__ __align__(16) __half g_F0lo[BATCH * FEAT];
__device__ __align__(16) float  g_F1[BATCH * FEAT];

// ---------------------------------------------------------------------------
// fp16 mma.sync GEMM, 3-stage cp.async ring.  Optional 2-term split on A:
//   SPLIT_A=1: acc = Ahi*B + Alo*B   (activation exact to 22 bits)
//   SPLIT_A=0: acc = A*B
// MODE 0: K1 (bias+relu, split-fp16 out)
// MODE 1: K2 (bias; z=0 -> split F0, z=1 -> fp32 F1)
// MODE 2: K3 (fused final dot into out via atomics)
// ---------------------------------------------------------------------------
template <int BM, int BN, int THREADS, int KK, int NOUT, int MODE, int MINB, int SPLIT_A>
__global__ void __launch_bounds__(THREADS, MINB)
gemm_mma(const __half* __restrict__ Ahi, const __half* __restrict__ Alo,
         const __half* __restrict__ Bhi,
         const float* __restrict__ bias0, const float* __restrict__ bias1,
         __half* __restrict__ Ohi, __half* __restrict__ Olo,
         float* __restrict__ Ofa, float* __restrict__ Ofb)
{
    constexpr int BK   = 32;                  // halves per stage
    constexpr int ROWB = 80;                  // 64B data + 16B pad
    constexpr int T    = KK / BK;
    constexpr int WARPS = THREADS / 32;
    constexpr int WN_W = (BN == 128) ? 4 : 2;
    constexpr int WM_W = WARPS / WN_W;
    constexpr int WTM  = BM / WM_W;
    constexpr int WTN  = BN / WN_W;
    constexpr int MI   = WTM / 16;
    constexpr int NI   = WTN / 8;
    constexpr int ACOP = SPLIT_A ? 2 : 1;
    constexpr int STAGE = (ACOP * BM + BN) * ROWB;
    constexpr size_t AZ = (MODE == 0) ? (size_t)BATCH * IN_DIM
                         : (MODE == 1) ? (size_t)BATCH * HID : 0;
    constexpr size_t BZ = (MODE == 0) ? 0
                         : (MODE == 1) ? (size_t)FEAT * HID : (size_t)FEAT * FEAT;
    constexpr size_t OZ = (size_t)BATCH * NOUT;

    extern __shared__ char dsm[];
    const uint32_t sbase = smem_u32(dsm);

    const int tid  = threadIdx.x;
    const int lane = tid & 31;
    const int warp = tid >> 5;
    const int wm = warp / WN_W, wn = warp % WN_W;
    const int z = blockIdx.z;
    const int rowBlock = blockIdx.y * BM;
    const int colBlock = blockIdx.x * BN;

    Ahi += (size_t)z * AZ;
    if (SPLIT_A) Alo += (size_t)z * AZ;
    Bhi += (size_t)z * BZ;
    const float* bias = z ? bias1 : bias0;

    auto stage = [&](int t, int buf_i) {
        const int kt = t * BK;
        const uint32_t buf = sbase + buf_i * STAGE;
        #pragma unroll
        for (int i = 0; i < (BM * 4 + THREADS - 1) / THREADS; i++) {
            int slot = tid + i * THREADS;
            int row = slot >> 2, ch = slot & 3;
            uint32_t d = buf + row * ROWB + ch * 16;
            CP16(d, Ahi + (size_t)(rowBlock + row) * KK + kt + ch * 8);
            if (SPLIT_A)
                CP16(d + BM * ROWB, Alo + (size_t)(rowBlock + row) * KK + kt + ch * 8);
        }
        #pragma unroll
        for (int i = 0; i < (BN * 4 + THREADS - 1) / THREADS; i++) {
            int slot = tid + i * THREADS;
            int row = slot >> 2, ch = slot & 3;
            CP16(buf + (ACOP * BM + row) * ROWB + ch * 16,
                 Bhi + (size_t)(colBlock + row) * KK + kt + ch * 8);
        }
        CP_COMMIT();
    };

    float acc[MI][NI][4];
    #pragma unroll
    for (int mi = 0; mi < MI; mi++)
        #pragma unroll
        for (int ni = 0; ni < NI; ni++)
            #pragma unroll
            for (int r = 0; r < 4; r++) acc[mi][ni][r] = 0.0f;

    const uint32_t aOff = (uint32_t)((wm * WTM + (lane & 15)) * ROWB + (lane >> 4) * 16);
    const uint32_t bOff = (uint32_t)((wn * WTN + ((lane >> 4) << 3) + (lane & 7)) * ROWB
                                     + ((lane >> 3) & 1) * 16);

    // 3-stage ring
    stage(0, 0);
    stage(1, 1);
    int bc = 0, bn2 = 2;

    #pragma unroll 1
    for (int t = 0; t < T; t++) {
        CP_WAIT1();
        __syncthreads();
        if (t + 2 < T) stage(t + 2, bn2);

        const uint32_t buf  = sbase + bc * STAGE;
        const uint32_t aHiB = buf + aOff;
        const uint32_t aLoB = aHiB + BM * ROWB;
        const uint32_t bHiB = buf + ACOP * BM * ROWB + bOff;

        #pragma unroll
        for (int ks = 0; ks < 2; ks++) {
            const uint32_t ko = ks * 32;   // 16 halves = 32B
            uint32_t ah[MI][4], al[MI][4];
            #pragma unroll
            for (int mi = 0; mi < MI; mi++) {
                LDSM4(ah[mi][0], ah[mi][1], ah[mi][2], ah[mi][3],
                      aHiB + mi * 16 * ROWB + ko);
                if (SPLIT_A)
                    LDSM4(al[mi][0], al[mi][1], al[mi][2], al[mi][3],
                          aLoB + mi * 16 * ROWB + ko);
            }
            uint32_t bh[NI][2];
            #pragma unroll
            for (int np = 0; np < NI / 2; np++) {
                LDSM4(bh[np * 2][0], bh[np * 2][1], bh[np * 2 + 1][0], bh[np * 2 + 1][1],
                      bHiB + np * 16 * ROWB + ko);
            }
            #pragma unroll
            for (int mi = 0; mi < MI; mi++)
                #pragma unroll
                for (int ni = 0; ni < NI; ni++) {
                    mma16816(acc[mi][ni], ah[mi], bh[ni]);
                    if (SPLIT_A) mma16816(acc[mi][ni], al[mi], bh[ni]);
                }
        }
        bc = (bc == 2) ? 0 : bc + 1;
        bn2 = (bn2 == 2) ? 0 : bn2 + 1;
    }

    // ------------------------------ epilogue --------------------------------
    const int g  = lane >> 2;
    const int kq = lane & 3;
    #pragma unroll
    for (int mi = 0; mi < MI; mi++) {
        #pragma unroll
        for (int half = 0; half < 2; half++) {
            const int grow = rowBlock + wm * WTM + mi * 16 + half * 8 + g;
            if (MODE == 2) {
                const float* F1p = Ofa;
                float s = 0.0f;
                #pragma unroll
                for (int ni = 0; ni < NI; ni++) {
                    const int gc = colBlock + wn * WTN + ni * 8 + kq * 2;
                    float2 fv = *reinterpret_cast<const float2*>(
                        F1p + (size_t)grow * FEAT + gc);
                    s = fmaf(acc[mi][ni][half * 2 + 0], fv.x,
                        fmaf(acc[mi][ni][half * 2 + 1], fv.y, s));
                }
                s += __shfl_xor_sync(0xFFFFFFFFu, s, 1);
                s += __shfl_xor_sync(0xFFFFFFFFu, s, 2);
                if (kq == 0) atomicAdd(&Ofb[grow * 2 + z], s);
            } else {
                #pragma unroll
                for (int ni = 0; ni < NI; ni++) {
                    const int gc = colBlock + wn * WTN + ni * 8 + kq * 2;
                    float v0 = acc[mi][ni][half * 2 + 0] + bias[gc];
                    float v1 = acc[mi][ni][half * 2 + 1] + bias[gc + 1];
                    if (MODE == 0) { v0 = fmaxf(v0, 0.0f); v1 = fmaxf(v1, 0.0f); }
                    const size_t base = (size_t)grow * NOUT + gc;
                    if (MODE == 0 || z == 0) {
                        __half h0 = __float2half(v0);
                        __half h1 = __float2half(v1);
                        __half l0 = __float2half(v0 - __half2float(h0));
                        __half l1 = __float2half(v1 - __half2float(h1));
                        __half* oh = Ohi;
                        __half* ol = Olo;
                        if (MODE == 0) { oh += (size_t)z * OZ; ol += (size_t)z * OZ; }
                        *reinterpret_cast<__half2*>(oh + base) = __halves2half2(h0, h1);
                        *reinterpret_cast<__half2*>(ol + base) = __halves2half2(l0, l1);
                    } else {
                        *reinterpret_cast<float2*>(Ofa + base) = make_float2(v0, v1);
                    }
                }
            }
        }
    }
}

// ---------------------------------------------------------------------------
// Unified prep kernel: x -> plain fp16, weight transposes, W_out repack,
// out bias-init.
// ---------------------------------------------------------------------------
#define XB 2048
#define WF_TILES 512
#define WB_TILES 256
#define WO_BLKS 64
#define OI_BLKS 4

__device__ __forceinline__ void transpose_tile(
    const float* __restrict__ W, __half* __restrict__ hi,
    int Krows, int Ncols, int bxn, int byk, float (*tile)[33], int tid)
{
    int tx = tid & 31, ty = tid >> 5;
    int n0 = bxn * 32, k0 = byk * 32;
    #pragma unroll
    for (int i = 0; i < 32; i += 8)
        tile[ty + i][tx] = W[(size_t)(k0 + ty + i) * Ncols + n0 + tx];
    __syncthreads();
    #pragma unroll
    for (int i = 0; i < 32; i += 8)
        hi[(size_t)(n0 + ty + i) * Krows + k0 + tx] = __float2half(tile[tx][ty + i]);
}

__global__ void __launch_bounds__(256)
prep_kernel(const float* __restrict__ x0, const float* __restrict__ x1,
            const float* __restrict__ W_feat,
            const float* __restrict__ W_br0, const float* __restrict__ W_br1,
            const float* __restrict__ W_out, const float* __restrict__ b_out,
            __half* __restrict__ Xhi,
            __half* __restrict__ Wfhi, __half* __restrict__ Wbhi,
            __half* __restrict__ Wohi, float* __restrict__ out)
{
    __shared__ float tile[32][33];
    const int tid = threadIdx.x;
    int bx = blockIdx.x;

    if (bx < 2 * XB) {
        const float* src = (bx < XB) ? x0 : x1;
        size_t zoff = (bx < XB) ? 0 : (size_t)BATCH * IN_DIM;
        int i = (bx & (XB - 1)) * 256 + tid;
        float4 v = reinterpret_cast<const float4*>(src)[i];
        __half2* hp = reinterpret_cast<__half2*>(Xhi + zoff) + (size_t)i * 2;
        hp[0] = __halves2half2(__float2half(v.x), __float2half(v.y));
        hp[1] = __halves2half2(__float2half(v.z), __float2half(v.w));
    } else if (bx < 2 * XB + WF_TILES) {
        int t = bx - 2 * XB;
        transpose_tile(W_feat, Wfhi, IN_DIM, HID, t & 15, t >> 4, tile, tid);
    } else if (bx < 2 * XB + WF_TILES + WB_TILES) {
        int t = bx - (2 * XB + WF_TILES);
        int zz = t >> 7; t &= 127;
        transpose_tile(zz ? W_br1 : W_br0, Wbhi + (size_t)zz * FEAT * HID,
                       HID, FEAT, t & 7, t >> 3, tile, tid);
    } else if (bx < 2 * XB + WF_TILES + WB_TILES + WO_BLKS) {
        int t = bx - (2 * XB + WF_TILES + WB_TILES);
        int r = t * 1024 + tid * 4;
        #pragma unroll
        for (int q = 0; q < 4; q++) {
            float2 w = reinterpret_cast<const float2*>(W_out)[r + q];
            Wohi[r + q]                = __float2half(w.x);
            Wohi[FEAT * FEAT + r + q]  = __float2half(w.y);
        }
    } else {
        int t = bx - (2 * XB + WF_TILES + WB_TILES + WO_BLKS);
        int i = t * 1024 + tid * 4;
        float b0 = b_out[0], b1 = b_out[1];
        #pragma unroll
        for (int q = 0; q < 4; q++) out[i + q] = ((i + q) & 1) ? b1 : b0;
    }
}

// ---------------------------- launch ----------------------------------------
extern "C" void kernel_launch(void* const* d_in, const int* in_sizes, int n_in,
                              void* d_out, int out_size)
{
    const float* x0     = (const float*)d_in[0];
    const float* x1     = (const float*)d_in[1];
    const float* W_feat = (const float*)d_in[2];
    const float* b_feat = (const float*)d_in[3];
    const float* W_br0  = (const float*)d_in[4];
    const float* b_br0  = (const float*)d_in[5];
    const float* W_br1  = (const float*)d_in[6];
    const float* b_br1  = (const float*)d_in[7];
    const float* W_out  = (const float*)d_in[8];
    const float* b_out  = (const float*)d_in[9];
    float*       out    = (float*)d_out;

    __half *Xhi, *Wfhi, *Wbhi, *Wohi, *Hhi, *Hlo, *F0hi, *F0lo;
    float *F1;
    cudaGetSymbolAddress((void**)&Xhi, g_Xhi);
    cudaGetSymbolAddress((void**)&Wfhi, g_Wfhi);
    cudaGetSymbolAddress((void**)&Wbhi, g_Wbhi);
    cudaGetSymbolAddress((void**)&Wohi, g_Wohi);
    cudaGetSymbolAddress((void**)&Hhi, g_Hhi);   cudaGetSymbolAddress((void**)&Hlo, g_Hlo);
    cudaGetSymbolAddress((void**)&F0hi, g_F0hi); cudaGetSymbolAddress((void**)&F0lo, g_F0lo);
    cudaGetSymbolAddress((void**)&F1, g_F1);

    // K1 (SPLIT_A=0): stage (64 + 128)*80 = 15360, x3 = 46080
    // K2/K3 (SPLIT_A=1): stage (2*32 + 64)*80 = 10240, x3 = 30720
    constexpr int SM1 = 3 * (64 + 128) * 80;
    constexpr int SM2 = 3 * (2 * 32 + 64) * 80;
    cudaFuncSetAttribute((const void*)gemm_mma<64, 128, 256, 1024, 512, 0, 2, 0>,
                         cudaFuncAttributeMaxDynamicSharedMemorySize, SM1);
    cudaFuncSetAttribute((const void*)gemm_mma<32, 64, 128, 512, 256, 1, 4, 1>,
                         cudaFuncAttributeMaxDynamicSharedMemorySize, SM2);
    cudaFuncSetAttribute((const void*)gemm_mma<32, 64, 128, 256, 256, 2, 4, 1>,
                         cudaFuncAttributeMaxDynamicSharedMemorySize, SM2);

    prep_kernel<<<2 * XB + WF_TILES + WB_TILES + WO_BLKS + OI_BLKS, 256>>>(
        x0, x1, W_feat, W_br0, W_br1, W_out, b_out,
        Xhi, Wfhi, Wbhi, Wohi, out);

    // K1: plain fp16 A; grid (4, 32, 2) = 256 CTAs x 8 warps
    gemm_mma<64, 128, 256, 1024, 512, 0, 2, 0>
        <<<dim3(HID / 128, BATCH / 64, 2), 256, SM1>>>(
        Xhi, nullptr, Wfhi, b_feat, b_feat, Hhi, Hlo, nullptr, nullptr);

    // K2: split-A (H); grid (4, 64, 2) = 512 CTAs x 4 warps
    gemm_mma<32, 64, 128, 512, 256, 1, 4, 1>
        <<<dim3(FEAT / 64, BATCH / 32, 2), 128, SM2>>>(
        Hhi, Hlo, Wbhi, b_br0, b_br1, F0hi, F0lo, F1, nullptr);

    // K3 (+fused K4): split-A (F0); 512 CTAs x 4 warps
    gemm_mma<32, 64, 128, 256, 256, 2, 4, 1>
        <<<dim3(FEAT / 64, BATCH / 32, 2), 128, SM2>>>(
        F0hi, F0lo, Wohi, nullptr, nullptr, nullptr, nullptr, F1, out);
}

// round 10
// speedup vs baseline: 5.5163x; 1.1223x over previous
#include <cuda_runtime.h>
#include <cuda_fp16.h>
#include <cstdint>

#define BATCH   2048
#define IN_DIM  1024
#define HID     512
#define FEAT    256

// ---------------------------------------------------------------------------
// helpers
// ---------------------------------------------------------------------------
__device__ __forceinline__ uint32_t smem_u32(const void* p) {
    uint32_t a;
    asm("{ .reg .u64 t; cvta.to.shared.u64 t, %1; cvt.u32.u64 %0, t; }"
        : "=r"(a) : "l"(p));
    return a;
}

__device__ __forceinline__ void mma16816(float* c, const uint32_t* a, const uint32_t* b)
{
    asm volatile(
        "mma.sync.aligned.m16n8k16.row.col.f32.f16.f16.f32 "
        "{%0,%1,%2,%3}, {%4,%5,%6,%7}, {%8,%9}, {%0,%1,%2,%3};\n"
        : "+f"(c[0]), "+f"(c[1]), "+f"(c[2]), "+f"(c[3])
        : "r"(a[0]), "r"(a[1]), "r"(a[2]), "r"(a[3]), "r"(b[0]), "r"(b[1]));
}

#define LDSM4(r0, r1, r2, r3, addr)                                            \
    asm volatile("ldmatrix.sync.aligned.m8n8.x4.shared.b16 {%0,%1,%2,%3}, [%4];" \
        : "=r"(r0), "=r"(r1), "=r"(r2), "=r"(r3) : "r"(addr))

#define CP16(dst, src)                                                         \
    asm volatile("cp.async.cg.shared.global [%0], [%1], 16;"                   \
        :: "r"(dst), "l"(src))
#define CP_COMMIT() asm volatile("cp.async.commit_group;" ::: "memory")
#define CP_WAIT1()  asm volatile("cp.async.wait_group 1;" ::: "memory")
#define CP_WAIT0()  asm volatile("cp.async.wait_group 0;" ::: "memory")

// ---------------------------- scratch ---------------------------------------
__device__ __align__(16) __half g_X[2 * BATCH * IN_DIM];      // fp16 x
__device__ __align__(16) __half g_Wf[HID * IN_DIM];           // [N=512][K=1024]
__device__ __align__(16) __half g_Wb[2 * FEAT * HID];         // [z][N=256][K=512]
__device__ __align__(16) __half g_Wo[2 * FEAT * FEAT];        // [o][j][i]
__device__ __align__(16) __half g_H[2 * BATCH * HID];
__device__ __align__(16) __half g_F0[BATCH * FEAT];
__device__ __align__(16) float  g_F1[BATCH * FEAT];

// ---------------------------------------------------------------------------
// fp16 mma.sync GEMM, 3-stage cp.async ring.  acc fp32 = A*B.
// RACE FIX: final iteration must wait_group(0) — the tile being read IS the
// newest committed group there; wait_group(1) would allow reading it in-flight.
// MODE 0: K1 (bias+relu, fp16 out)
// MODE 1: K2 (bias; z=0 -> fp16 F0, z=1 -> fp32 F1)
// MODE 2: K3 (fused final dot into out via atomics)
// ---------------------------------------------------------------------------
template <int BM, int BN, int THREADS, int KK, int NOUT, int MODE, int MINB>
__global__ void __launch_bounds__(THREADS, MINB)
gemm_mma(const __half* __restrict__ A, const __half* __restrict__ B,
         const float* __restrict__ bias0, const float* __restrict__ bias1,
         __half* __restrict__ Oh, float* __restrict__ Ofa, float* __restrict__ Ofb)
{
    constexpr int BK   = 32;                  // halves per stage
    constexpr int ROWB = 80;                  // 64B data + 16B pad
    constexpr int T    = KK / BK;
    constexpr int WARPS = THREADS / 32;
    constexpr int WN_W = (BN == 128) ? 4 : 2;
    constexpr int WM_W = WARPS / WN_W;
    constexpr int WTM  = BM / WM_W;
    constexpr int WTN  = BN / WN_W;
    constexpr int MI   = WTM / 16;
    constexpr int NI   = WTN / 8;
    constexpr int STAGE = (BM + BN) * ROWB;
    constexpr size_t AZ = (MODE == 0) ? (size_t)BATCH * IN_DIM
                         : (MODE == 1) ? (size_t)BATCH * HID : 0;
    constexpr size_t BZ = (MODE == 0) ? 0
                         : (MODE == 1) ? (size_t)FEAT * HID : (size_t)FEAT * FEAT;
    constexpr size_t OZ = (size_t)BATCH * NOUT;

    extern __shared__ char dsm[];
    const uint32_t sbase = smem_u32(dsm);

    const int tid  = threadIdx.x;
    const int lane = tid & 31;
    const int warp = tid >> 5;
    const int wm = warp / WN_W, wn = warp % WN_W;
    const int z = blockIdx.z;
    const int rowBlock = blockIdx.y * BM;
    const int colBlock = blockIdx.x * BN;

    A += (size_t)z * AZ;
    B += (size_t)z * BZ;
    const float* bias = z ? bias1 : bias0;

    auto stage = [&](int t, int buf_i) {
        const int kt = t * BK;
        const uint32_t buf = sbase + buf_i * STAGE;
        #pragma unroll
        for (int i = 0; i < (BM * 4 + THREADS - 1) / THREADS; i++) {
            int slot = tid + i * THREADS;
            int row = slot >> 2, ch = slot & 3;
            CP16(buf + row * ROWB + ch * 16,
                 A + (size_t)(rowBlock + row) * KK + kt + ch * 8);
        }
        #pragma unroll
        for (int i = 0; i < (BN * 4 + THREADS - 1) / THREADS; i++) {
            int slot = tid + i * THREADS;
            int row = slot >> 2, ch = slot & 3;
            CP16(buf + (BM + row) * ROWB + ch * 16,
                 B + (size_t)(colBlock + row) * KK + kt + ch * 8);
        }
        CP_COMMIT();
    };

    float acc[MI][NI][4];
    #pragma unroll
    for (int mi = 0; mi < MI; mi++)
        #pragma unroll
        for (int ni = 0; ni < NI; ni++)
            #pragma unroll
            for (int r = 0; r < 4; r++) acc[mi][ni][r] = 0.0f;

    const uint32_t aOff = (uint32_t)((wm * WTM + (lane & 15)) * ROWB + (lane >> 4) * 16);
    const uint32_t bOff = (uint32_t)((wn * WTN + ((lane >> 4) << 3) + (lane & 7)) * ROWB
                                     + ((lane >> 3) & 1) * 16);

    // 3-stage ring
    stage(0, 0);
    stage(1, 1);
    int bc = 0, bn2 = 2;

    #pragma unroll 1
    for (int t = 0; t < T; t++) {
        // RACE FIX: at t == T-1 the tile we read is the newest group.
        if (t + 1 < T) { CP_WAIT1(); } else { CP_WAIT0(); }
        __syncthreads();
        if (t + 2 < T) stage(t + 2, bn2);

        const uint32_t buf  = sbase + bc * STAGE;
        const uint32_t aB = buf + aOff;
        const uint32_t bB = buf + BM * ROWB + bOff;

        #pragma unroll
        for (int ks = 0; ks < 2; ks++) {
            const uint32_t ko = ks * 32;   // 16 halves = 32B
            uint32_t ah[MI][4];
            #pragma unroll
            for (int mi = 0; mi < MI; mi++)
                LDSM4(ah[mi][0], ah[mi][1], ah[mi][2], ah[mi][3],
                      aB + mi * 16 * ROWB + ko);
            uint32_t bh[NI][2];
            #pragma unroll
            for (int np = 0; np < NI / 2; np++)
                LDSM4(bh[np * 2][0], bh[np * 2][1], bh[np * 2 + 1][0], bh[np * 2 + 1][1],
                      bB + np * 16 * ROWB + ko);
            #pragma unroll
            for (int mi = 0; mi < MI; mi++)
                #pragma unroll
                for (int ni = 0; ni < NI; ni++)
                    mma16816(acc[mi][ni], ah[mi], bh[ni]);
        }
        bc = (bc == 2) ? 0 : bc + 1;
        bn2 = (bn2 == 2) ? 0 : bn2 + 1;
    }

    // ------------------------------ epilogue --------------------------------
    const int g  = lane >> 2;
    const int kq = lane & 3;
    #pragma unroll
    for (int mi = 0; mi < MI; mi++) {
        #pragma unroll
        for (int half = 0; half < 2; half++) {
            const int grow = rowBlock + wm * WTM + mi * 16 + half * 8 + g;
            if (MODE == 2) {
                const float* F1p = Ofa;
                float s = 0.0f;
                #pragma unroll
                for (int ni = 0; ni < NI; ni++) {
                    const int gc = colBlock + wn * WTN + ni * 8 + kq * 2;
                    float2 fv = *reinterpret_cast<const float2*>(
                        F1p + (size_t)grow * FEAT + gc);
                    s = fmaf(acc[mi][ni][half * 2 + 0], fv.x,
                        fmaf(acc[mi][ni][half * 2 + 1], fv.y, s));
                }
                s += __shfl_xor_sync(0xFFFFFFFFu, s, 1);
                s += __shfl_xor_sync(0xFFFFFFFFu, s, 2);
                if (kq == 0) atomicAdd(&Ofb[grow * 2 + z], s);
            } else {
                #pragma unroll
                for (int ni = 0; ni < NI; ni++) {
                    const int gc = colBlock + wn * WTN + ni * 8 + kq * 2;
                    float v0 = acc[mi][ni][half * 2 + 0] + bias[gc];
                    float v1 = acc[mi][ni][half * 2 + 1] + bias[gc + 1];
                    if (MODE == 0) { v0 = fmaxf(v0, 0.0f); v1 = fmaxf(v1, 0.0f); }
                    const size_t base = (size_t)grow * NOUT + gc;
                    if (MODE == 0 || z == 0) {
                        __half* oh = Oh;
                        if (MODE == 0) oh += (size_t)z * OZ;
                        *reinterpret_cast<__half2*>(oh + base) =
                            __halves2half2(__float2half(v0), __float2half(v1));
                    } else {
                        *reinterpret_cast<float2*>(Ofa + base) = make_float2(v0, v1);
                    }
                }
            }
        }
    }
}

// ---------------------------------------------------------------------------
// Unified prep kernel
// ---------------------------------------------------------------------------
#define XB 2048
#define WF_TILES 512
#define WB_TILES 256
#define WO_BLKS 64
#define OI_BLKS 4

__device__ __forceinline__ void transpose_tile(
    const float* __restrict__ W, __half* __restrict__ hi,
    int Krows, int Ncols, int bxn, int byk, float (*tile)[33], int tid)
{
    int tx = tid & 31, ty = tid >> 5;
    int n0 = bxn * 32, k0 = byk * 32;
    #pragma unroll
    for (int i = 0; i < 32; i += 8)
        tile[ty + i][tx] = W[(size_t)(k0 + ty + i) * Ncols + n0 + tx];
    __syncthreads();
    #pragma unroll
    for (int i = 0; i < 32; i += 8)
        hi[(size_t)(n0 + ty + i) * Krows + k0 + tx] = __float2half(tile[tx][ty + i]);
}

__global__ void __launch_bounds__(256)
prep_kernel(const float* __restrict__ x0, const float* __restrict__ x1,
            const float* __restrict__ W_feat,
            const float* __restrict__ W_br0, const float* __restrict__ W_br1,
            const float* __restrict__ W_out, const float* __restrict__ b_out,
            __half* __restrict__ X,
            __half* __restrict__ Wf, __half* __restrict__ Wb,
            __half* __restrict__ Wo, float* __restrict__ out)
{
    __shared__ float tile[32][33];
    const int tid = threadIdx.x;
    int bx = blockIdx.x;

    if (bx < 2 * XB) {
        const float* src = (bx < XB) ? x0 : x1;
        size_t zoff = (bx < XB) ? 0 : (size_t)BATCH * IN_DIM;
        int i = (bx & (XB - 1)) * 256 + tid;
        float4 v = reinterpret_cast<const float4*>(src)[i];
        __half2* hp = reinterpret_cast<__half2*>(X + zoff) + (size_t)i * 2;
        hp[0] = __halves2half2(__float2half(v.x), __float2half(v.y));
        hp[1] = __halves2half2(__float2half(v.z), __float2half(v.w));
    } else if (bx < 2 * XB + WF_TILES) {
        int t = bx - 2 * XB;
        transpose_tile(W_feat, Wf, IN_DIM, HID, t & 15, t >> 4, tile, tid);
    } else if (bx < 2 * XB + WF_TILES + WB_TILES) {
        int t = bx - (2 * XB + WF_TILES);
        int zz = t >> 7; t &= 127;
        transpose_tile(zz ? W_br1 : W_br0, Wb + (size_t)zz * FEAT * HID,
                       HID, FEAT, t & 7, t >> 3, tile, tid);
    } else if (bx < 2 * XB + WF_TILES + WB_TILES + WO_BLKS) {
        int t = bx - (2 * XB + WF_TILES + WB_TILES);
        int r = t * 1024 + tid * 4;
        #pragma unroll
        for (int q = 0; q < 4; q++) {
            float2 w = reinterpret_cast<const float2*>(W_out)[r + q];
            Wo[r + q]               = __float2half(w.x);
            Wo[FEAT * FEAT + r + q] = __float2half(w.y);
        }
    } else {
        int t = bx - (2 * XB + WF_TILES + WB_TILES + WO_BLKS);
        int i = t * 1024 + tid * 4;
        float b0 = b_out[0], b1 = b_out[1];
        #pragma unroll
        for (int q = 0; q < 4; q++) out[i + q] = ((i + q) & 1) ? b1 : b0;
    }
}

// ---------------------------- launch ----------------------------------------
extern "C" void kernel_launch(void* const* d_in, const int* in_sizes, int n_in,
                              void* d_out, int out_size)
{
    const float* x0     = (const float*)d_in[0];
    const float* x1     = (const float*)d_in[1];
    const float* W_feat = (const float*)d_in[2];
    const float* b_feat = (const float*)d_in[3];
    const float* W_br0  = (const float*)d_in[4];
    const float* b_br0  = (const float*)d_in[5];
    const float* W_br1  = (const float*)d_in[6];
    const float* b_br1  = (const float*)d_in[7];
    const float* W_out  = (const float*)d_in[8];
    const float* b_out  = (const float*)d_in[9];
    float*       out    = (float*)d_out;

    __half *X, *Wf, *Wb, *Wo, *H, *F0;
    float *F1;
    cudaGetSymbolAddress((void**)&X, g_X);
    cudaGetSymbolAddress((void**)&Wf, g_Wf);
    cudaGetSymbolAddress((void**)&Wb, g_Wb);
    cudaGetSymbolAddress((void**)&Wo, g_Wo);
    cudaGetSymbolAddress((void**)&H, g_H);
    cudaGetSymbolAddress((void**)&F0, g_F0);
    cudaGetSymbolAddress((void**)&F1, g_F1);

    // K1: stage (64+128)*80 = 15360, x3 = 46080
    // K2/K3: stage (32+64)*80 = 7680, x3 = 23040
    constexpr int SM1 = 3 * (64 + 128) * 80;
    constexpr int SM2 = 3 * (32 + 64) * 80;
    cudaFuncSetAttribute((const void*)gemm_mma<64, 128, 256, 1024, 512, 0, 2>,
                         cudaFuncAttributeMaxDynamicSharedMemorySize, SM1);
    cudaFuncSetAttribute((const void*)gemm_mma<32, 64, 128, 512, 256, 1, 4>,
                         cudaFuncAttributeMaxDynamicSharedMemorySize, SM2);
    cudaFuncSetAttribute((const void*)gemm_mma<32, 64, 128, 256, 256, 2, 4>,
                         cudaFuncAttributeMaxDynamicSharedMemorySize, SM2);

    prep_kernel<<<2 * XB + WF_TILES + WB_TILES + WO_BLKS + OI_BLKS, 256>>>(
        x0, x1, W_feat, W_br0, W_br1, W_out, b_out, X, Wf, Wb, Wo, out);

    // K1: grid (4, 32, 2) = 256 CTAs x 8 warps
    gemm_mma<64, 128, 256, 1024, 512, 0, 2>
        <<<dim3(HID / 128, BATCH / 64, 2), 256, SM1>>>(
        X, Wf, b_feat, b_feat, H, nullptr, nullptr);

    // K2: grid (4, 64, 2) = 512 CTAs x 4 warps
    gemm_mma<32, 64, 128, 512, 256, 1, 4>
        <<<dim3(FEAT / 64, BATCH / 32, 2), 128, SM2>>>(
        H, Wb, b_br0, b_br1, F0, F1, nullptr);

    // K3 (+fused K4): 512 CTAs x 4 warps
    gemm_mma<32, 64, 128, 256, 256, 2, 4>
        <<<dim3(FEAT / 64, BATCH / 32, 2), 128, SM2>>>(
        F0, Wo, nullptr, nullptr, nullptr, F1, out);
}

// round 11
// speedup vs baseline: 6.0828x; 1.1027x over previous
#include <cuda_runtime.h>
#include <cuda_fp16.h>
#include <cstdint>

#define BATCH   2048
#define IN_DIM  1024
#define HID     512
#define FEAT    256

// ---------------------------------------------------------------------------
// helpers
// ---------------------------------------------------------------------------
__device__ __forceinline__ uint32_t smem_u32(const void* p) {
    uint32_t a;
    asm("{ .reg .u64 t; cvta.to.shared.u64 t, %1; cvt.u32.u64 %0, t; }"
        : "=r"(a) : "l"(p));
    return a;
}

__device__ __forceinline__ void mma16816(float* c, const uint32_t* a, const uint32_t* b)
{
    asm volatile(
        "mma.sync.aligned.m16n8k16.row.col.f32.f16.f16.f32 "
        "{%0,%1,%2,%3}, {%4,%5,%6,%7}, {%8,%9}, {%0,%1,%2,%3};\n"
        : "+f"(c[0]), "+f"(c[1]), "+f"(c[2]), "+f"(c[3])
        : "r"(a[0]), "r"(a[1]), "r"(a[2]), "r"(a[3]), "r"(b[0]), "r"(b[1]));
}

#define LDSM4(r0, r1, r2, r3, addr)                                            \
    asm volatile("ldmatrix.sync.aligned.m8n8.x4.shared.b16 {%0,%1,%2,%3}, [%4];" \
        : "=r"(r0), "=r"(r1), "=r"(r2), "=r"(r3) : "r"(addr))

#define CP16(dst, src)                                                         \
    asm volatile("cp.async.cg.shared.global [%0], [%1], 16;"                   \
        :: "r"(dst), "l"(src))
#define CP_COMMIT() asm volatile("cp.async.commit_group;" ::: "memory")
#define CP_WAIT1()  asm volatile("cp.async.wait_group 1;" ::: "memory")
#define CP_WAIT0()  asm volatile("cp.async.wait_group 0;" ::: "memory")

// ---------------------------- scratch ---------------------------------------
__device__ __align__(16) __half g_X[2 * BATCH * IN_DIM];      // fp16 x
__device__ __align__(16) __half g_Wf[HID * IN_DIM];           // [N=512][K=1024]
__device__ __align__(16) __half g_Wb[2 * FEAT * HID];         // [z][N=256][K=512]
__device__ __align__(16) __half g_Wo[2 * FEAT * FEAT];        // [o][j][i]
__device__ __align__(16) __half g_H[2 * BATCH * HID];
__device__ __align__(16) __half g_F0[BATCH * FEAT];
__device__ __align__(16) float  g_F1[BATCH * FEAT];

// ---------------------------------------------------------------------------
// fp16 mma.sync GEMM.  BK=128 k-tiles, 2-stage double buffer:
//   stage t lives in buf t&1; after computing buf b we sync, then re-stage
//   into b.  wait_group(1) while the other buffer is in flight; wait_group(0)
//   on the final tile (no in-flight read race).
// MODE 0: K1 (bias+relu, fp16 out)
// MODE 1: K2 (bias; z=0 -> fp16 F0, z=1 -> fp32 F1)
// MODE 2: K3 (fused final dot into out via atomics)
// ---------------------------------------------------------------------------
template <int BM, int BN, int THREADS, int KK, int NOUT, int MODE, int MINB>
__global__ void __launch_bounds__(THREADS, MINB)
gemm_mma(const __half* __restrict__ A, const __half* __restrict__ B,
         const float* __restrict__ bias0, const float* __restrict__ bias1,
         __half* __restrict__ Oh, float* __restrict__ Ofa, float* __restrict__ Ofb)
{
    constexpr int BK   = 128;                 // halves per stage
    constexpr int CHNK = BK / 8;              // 16B chunks per row = 16
    constexpr int ROWB = BK * 2 + 16;         // 256B data + 16B pad = 272
    constexpr int T    = KK / BK;
    constexpr int WARPS = THREADS / 32;
    constexpr int WN_W = (BN == 128) ? 4 : 2;
    constexpr int WM_W = WARPS / WN_W;
    constexpr int WTM  = BM / WM_W;
    constexpr int WTN  = BN / WN_W;
    constexpr int MI   = WTM / 16;
    constexpr int NI   = WTN / 8;
    constexpr int STAGE = (BM + BN) * ROWB;
    constexpr size_t AZ = (MODE == 0) ? (size_t)BATCH * IN_DIM
                         : (MODE == 1) ? (size_t)BATCH * HID : 0;
    constexpr size_t BZ = (MODE == 0) ? 0
                         : (MODE == 1) ? (size_t)FEAT * HID : (size_t)FEAT * FEAT;
    constexpr size_t OZ = (size_t)BATCH * NOUT;

    extern __shared__ char dsm[];
    const uint32_t sbase = smem_u32(dsm);

    const int tid  = threadIdx.x;
    const int lane = tid & 31;
    const int warp = tid >> 5;
    const int wm = warp / WN_W, wn = warp % WN_W;
    const int z = blockIdx.z;
    const int rowBlock = blockIdx.y * BM;
    const int colBlock = blockIdx.x * BN;

    A += (size_t)z * AZ;
    B += (size_t)z * BZ;
    const float* bias = z ? bias1 : bias0;

    auto stage = [&](int t, int buf_i) {
        const int kt = t * BK;
        const uint32_t buf = sbase + buf_i * STAGE;
        #pragma unroll
        for (int i = 0; i < BM * CHNK / THREADS; i++) {
            int slot = tid + i * THREADS;
            int row = slot / CHNK, ch = slot % CHNK;
            CP16(buf + row * ROWB + ch * 16,
                 A + (size_t)(rowBlock + row) * KK + kt + ch * 8);
        }
        #pragma unroll
        for (int i = 0; i < BN * CHNK / THREADS; i++) {
            int slot = tid + i * THREADS;
            int row = slot / CHNK, ch = slot % CHNK;
            CP16(buf + (BM + row) * ROWB + ch * 16,
                 B + (size_t)(colBlock + row) * KK + kt + ch * 8);
        }
        CP_COMMIT();
    };

    float acc[MI][NI][4];
    #pragma unroll
    for (int mi = 0; mi < MI; mi++)
        #pragma unroll
        for (int ni = 0; ni < NI; ni++)
            #pragma unroll
            for (int r = 0; r < 4; r++) acc[mi][ni][r] = 0.0f;

    const uint32_t aOff = (uint32_t)((wm * WTM + (lane & 15)) * ROWB + (lane >> 4) * 16);
    const uint32_t bOff = (uint32_t)((wn * WTN + ((lane >> 4) << 3) + (lane & 7)) * ROWB
                                     + ((lane >> 3) & 1) * 16);

    stage(0, 0);
    if (T > 1) stage(1, 1);

    #pragma unroll 1
    for (int t = 0; t < T; t++) {
        if (t + 1 < T) { CP_WAIT1(); } else { CP_WAIT0(); }
        __syncthreads();

        const uint32_t buf = sbase + (t & 1) * STAGE;
        const uint32_t aB = buf + aOff;
        const uint32_t bB = buf + BM * ROWB + bOff;

        #pragma unroll
        for (int ks = 0; ks < BK / 16; ks++) {
            const uint32_t ko = ks * 32;   // 16 halves = 32B
            uint32_t ah[MI][4];
            #pragma unroll
            for (int mi = 0; mi < MI; mi++)
                LDSM4(ah[mi][0], ah[mi][1], ah[mi][2], ah[mi][3],
                      aB + mi * 16 * ROWB + ko);
            uint32_t bh[NI][2];
            #pragma unroll
            for (int np = 0; np < NI / 2; np++)
                LDSM4(bh[np * 2][0], bh[np * 2][1], bh[np * 2 + 1][0], bh[np * 2 + 1][1],
                      bB + np * 16 * ROWB + ko);
            #pragma unroll
            for (int mi = 0; mi < MI; mi++)
                #pragma unroll
                for (int ni = 0; ni < NI; ni++)
                    mma16816(acc[mi][ni], ah[mi], bh[ni]);
        }

        // re-stage this buffer with tile t+2 (after everyone finished reading)
        if (t + 2 < T) {
            __syncthreads();
            stage(t + 2, t & 1);
        }
    }

    // ------------------------------ epilogue --------------------------------
    const int g  = lane >> 2;
    const int kq = lane & 3;
    #pragma unroll
    for (int mi = 0; mi < MI; mi++) {
        #pragma unroll
        for (int half = 0; half < 2; half++) {
            const int grow = rowBlock + wm * WTM + mi * 16 + half * 8 + g;
            if (MODE == 2) {
                const float* F1p = Ofa;
                float s = 0.0f;
                #pragma unroll
                for (int ni = 0; ni < NI; ni++) {
                    const int gc = colBlock + wn * WTN + ni * 8 + kq * 2;
                    float2 fv = *reinterpret_cast<const float2*>(
                        F1p + (size_t)grow * FEAT + gc);
                    s = fmaf(acc[mi][ni][half * 2 + 0], fv.x,
                        fmaf(acc[mi][ni][half * 2 + 1], fv.y, s));
                }
                s += __shfl_xor_sync(0xFFFFFFFFu, s, 1);
                s += __shfl_xor_sync(0xFFFFFFFFu, s, 2);
                if (kq == 0) atomicAdd(&Ofb[grow * 2 + z], s);
            } else {
                #pragma unroll
                for (int ni = 0; ni < NI; ni++) {
                    const int gc = colBlock + wn * WTN + ni * 8 + kq * 2;
                    float v0 = acc[mi][ni][half * 2 + 0] + bias[gc];
                    float v1 = acc[mi][ni][half * 2 + 1] + bias[gc + 1];
                    if (MODE == 0) { v0 = fmaxf(v0, 0.0f); v1 = fmaxf(v1, 0.0f); }
                    const size_t base = (size_t)grow * NOUT + gc;
                    if (MODE == 0 || z == 0) {
                        __half* oh = Oh;
                        if (MODE == 0) oh += (size_t)z * OZ;
                        *reinterpret_cast<__half2*>(oh + base) =
                            __halves2half2(__float2half(v0), __float2half(v1));
                    } else {
                        *reinterpret_cast<float2*>(Ofa + base) = make_float2(v0, v1);
                    }
                }
            }
        }
    }
}

// ---------------------------------------------------------------------------
// Unified prep kernel
// ---------------------------------------------------------------------------
#define XB 2048
#define WF_TILES 512
#define WB_TILES 256
#define WO_BLKS 64
#define OI_BLKS 4

__device__ __forceinline__ void transpose_tile(
    const float* __restrict__ W, __half* __restrict__ hi,
    int Krows, int Ncols, int bxn, int byk, float (*tile)[33], int tid)
{
    int tx = tid & 31, ty = tid >> 5;
    int n0 = bxn * 32, k0 = byk * 32;
    #pragma unroll
    for (int i = 0; i < 32; i += 8)
        tile[ty + i][tx] = W[(size_t)(k0 + ty + i) * Ncols + n0 + tx];
    __syncthreads();
    #pragma unroll
    for (int i = 0; i < 32; i += 8)
        hi[(size_t)(n0 + ty + i) * Krows + k0 + tx] = __float2half(tile[tx][ty + i]);
}

__global__ void __launch_bounds__(256)
prep_kernel(const float* __restrict__ x0, const float* __restrict__ x1,
            const float* __restrict__ W_feat,
            const float* __restrict__ W_br0, const float* __restrict__ W_br1,
            const float* __restrict__ W_out, const float* __restrict__ b_out,
            __half* __restrict__ X,
            __half* __restrict__ Wf, __half* __restrict__ Wb,
            __half* __restrict__ Wo, float* __restrict__ out)
{
    __shared__ float tile[32][33];
    const int tid = threadIdx.x;
    int bx = blockIdx.x;

    if (bx < 2 * XB) {
        const float* src = (bx < XB) ? x0 : x1;
        size_t zoff = (bx < XB) ? 0 : (size_t)BATCH * IN_DIM;
        int i = (bx & (XB - 1)) * 256 + tid;
        float4 v = reinterpret_cast<const float4*>(src)[i];
        __half2* hp = reinterpret_cast<__half2*>(X + zoff) + (size_t)i * 2;
        hp[0] = __halves2half2(__float2half(v.x), __float2half(v.y));
        hp[1] = __halves2half2(__float2half(v.z), __float2half(v.w));
    } else if (bx < 2 * XB + WF_TILES) {
        int t = bx - 2 * XB;
        transpose_tile(W_feat, Wf, IN_DIM, HID, t & 15, t >> 4, tile, tid);
    } else if (bx < 2 * XB + WF_TILES + WB_TILES) {
        int t = bx - (2 * XB + WF_TILES);
        int zz = t >> 7; t &= 127;
        transpose_tile(zz ? W_br1 : W_br0, Wb + (size_t)zz * FEAT * HID,
                       HID, FEAT, t & 7, t >> 3, tile, tid);
    } else if (bx < 2 * XB + WF_TILES + WB_TILES + WO_BLKS) {
        int t = bx - (2 * XB + WF_TILES + WB_TILES);
        int r = t * 1024 + tid * 4;
        #pragma unroll
        for (int q = 0; q < 4; q++) {
            float2 w = reinterpret_cast<const float2*>(W_out)[r + q];
            Wo[r + q]               = __float2half(w.x);
            Wo[FEAT * FEAT + r + q] = __float2half(w.y);
        }
    } else {
        int t = bx - (2 * XB + WF_TILES + WB_TILES + WO_BLKS);
        int i = t * 1024 + tid * 4;
        float b0 = b_out[0], b1 = b_out[1];
        #pragma unroll
        for (int q = 0; q < 4; q++) out[i + q] = ((i + q) & 1) ? b1 : b0;
    }
}

// ---------------------------- launch ----------------------------------------
extern "C" void kernel_launch(void* const* d_in, const int* in_sizes, int n_in,
                              void* d_out, int out_size)
{
    const float* x0     = (const float*)d_in[0];
    const float* x1     = (const float*)d_in[1];
    const float* W_feat = (const float*)d_in[2];
    const float* b_feat = (const float*)d_in[3];
    const float* W_br0  = (const float*)d_in[4];
    const float* b_br0  = (const float*)d_in[5];
    const float* W_br1  = (const float*)d_in[6];
    const float* b_br1  = (const float*)d_in[7];
    const float* W_out  = (const float*)d_in[8];
    const float* b_out  = (const float*)d_in[9];
    float*       out    = (float*)d_out;

    __half *X, *Wf, *Wb, *Wo, *H, *F0;
    float *F1;
    cudaGetSymbolAddress((void**)&X, g_X);
    cudaGetSymbolAddress((void**)&Wf, g_Wf);
    cudaGetSymbolAddress((void**)&Wb, g_Wb);
    cudaGetSymbolAddress((void**)&Wo, g_Wo);
    cudaGetSymbolAddress((void**)&H, g_H);
    cudaGetSymbolAddress((void**)&F0, g_F0);
    cudaGetSymbolAddress((void**)&F1, g_F1);

    // stage = (BM+BN) * 272 bytes, double-buffered:
    // K1:  (64+128)*272 = 52224  -> 104448
    // K2/K3: (32+64)*272 = 26112 ->  52224
    constexpr int SM1 = 2 * (64 + 128) * 272;
    constexpr int SM2 = 2 * (32 + 64) * 272;
    cudaFuncSetAttribute((const void*)gemm_mma<64, 128, 256, 1024, 512, 0, 2>,
                         cudaFuncAttributeMaxDynamicSharedMemorySize, SM1);
    cudaFuncSetAttribute((const void*)gemm_mma<32, 64, 128, 512, 256, 1, 4>,
                         cudaFuncAttributeMaxDynamicSharedMemorySize, SM2);
    cudaFuncSetAttribute((const void*)gemm_mma<32, 64, 128, 256, 256, 2, 4>,
                         cudaFuncAttributeMaxDynamicSharedMemorySize, SM2);

    prep_kernel<<<2 * XB + WF_TILES + WB_TILES + WO_BLKS + OI_BLKS, 256>>>(
        x0, x1, W_feat, W_br0, W_br1, W_out, b_out, X, Wf, Wb, Wo, out);

    // K1: grid (4, 32, 2) = 256 CTAs x 8 warps; T=8 stages
    gemm_mma<64, 128, 256, 1024, 512, 0, 2>
        <<<dim3(HID / 128, BATCH / 64, 2), 256, SM1>>>(
        X, Wf, b_feat, b_feat, H, nullptr, nullptr);

    // K2: grid (4, 64, 2) = 512 CTAs x 4 warps; T=4 stages
    gemm_mma<32, 64, 128, 512, 256, 1, 4>
        <<<dim3(FEAT / 64, BATCH / 32, 2), 128, SM2>>>(
        H, Wb, b_br0, b_br1, F0, F1, nullptr);

    // K3 (+fused K4): 512 CTAs x 4 warps; T=2 stages
    gemm_mma<32, 64, 128, 256, 256, 2, 4>
        <<<dim3(FEAT / 64, BATCH / 32, 2), 128, SM2>>>(
        F0, Wo, nullptr, nullptr, nullptr, F1, out);
}